// round 3
// baseline (speedup 1.0000x reference)
#include <cuda_runtime.h>
#include <cuda_bf16.h>

#define NN 100000
#define EE 3200000
#define NBLK 196   // ceil(NN/512)

// ---------------- scratch (device globals; no allocations) ----------------
__device__ float g_bufA[NN * 128];
__device__ float g_bufB[NN * 128];
__device__ float g_bufC[NN * 128];
__device__ float g_dinv[NN];
__device__ int   g_cnt[NN];
__device__ int   g_rowptr[NN + 1];
__device__ int   g_cols[EE];
__device__ int   g_bsum[256];
__device__ int   g_is64;

// ---------------- dtype detection for edge_index ----------------
// int64 little-endian values < 2^32 have all-odd 32-bit words == 0.
__global__ void k_detect(const unsigned int* __restrict__ ei_raw) {
    unsigned int o = 0;
    for (int i = 0; i < 2048; i++) o |= ei_raw[2 * i + 1];
    g_is64 = (o == 0u) ? 1 : 0;
}

__device__ __forceinline__ int load_edge(const void* ei, long long idx) {
    int v;
    if (g_is64) v = (int)((const long long*)ei)[idx];
    else        v = ((const int*)ei)[idx];
    // clamp for safety (bad index -> wrong answer, not a trap)
    return min(max(v, 0), NN - 1);
}

// ---------------- CSR build ----------------
__global__ void k_zero_cnt() {
    int i = blockIdx.x * blockDim.x + threadIdx.x;
    if (i < NN) g_cnt[i] = 0;
}

__global__ void k_hist(const void* __restrict__ ei) {
    int e = blockIdx.x * blockDim.x + threadIdx.x;
    if (e < EE) atomicAdd(&g_cnt[load_edge(ei, (long long)EE + e)], 1);
}

__global__ void k_scan1() {
    __shared__ int s[512];
    int t = threadIdx.x;
    int i = blockIdx.x * 512 + t;
    int v = (i < NN) ? g_cnt[i] : 0;
    s[t] = v;
    __syncthreads();
    for (int off = 1; off < 512; off <<= 1) {
        int x = (t >= off) ? s[t - off] : 0;
        __syncthreads();
        s[t] += x;
        __syncthreads();
    }
    if (i < NN) g_rowptr[i] = s[t] - v;   // exclusive
    if (t == 511) g_bsum[blockIdx.x] = s[511];
}

__global__ void k_scan2() {
    __shared__ int s[256];
    int t = threadIdx.x;
    int v = (t < NBLK) ? g_bsum[t] : 0;
    s[t] = v;
    __syncthreads();
    for (int off = 1; off < 256; off <<= 1) {
        int x = (t >= off) ? s[t - off] : 0;
        __syncthreads();
        s[t] += x;
        __syncthreads();
    }
    if (t < NBLK) g_bsum[t] = s[t] - v;   // exclusive block offsets
}

__global__ void k_scan3() {
    int i = blockIdx.x * blockDim.x + threadIdx.x;
    if (i < NN) {
        g_rowptr[i] += g_bsum[i >> 9];
        g_dinv[i] = rsqrtf((float)g_cnt[i] + 1.0f);
        g_cnt[i] = 0;                      // reuse as fill cursor
    }
    if (i == 0) g_rowptr[NN] = EE;
}

__global__ void k_fill(const void* __restrict__ ei) {
    int e = blockIdx.x * blockDim.x + threadIdx.x;
    if (e < EE) {
        int d = load_edge(ei, (long long)EE + e);
        int s = load_edge(ei, e);
        int p = atomicAdd(&g_cnt[d], 1);
        g_cols[g_rowptr[d] + p] = s;
    }
}

// ---------------- input projection: h = relu(x @ W_in + b_in) ----------------
__global__ __launch_bounds__(256) void k_inproj(
    const float* __restrict__ x, const float* __restrict__ Wi,
    const float* __restrict__ bi, float* __restrict__ h)
{
    __shared__ __align__(16) float Ws[7 * 128];
    for (int t = threadIdx.x; t < 7 * 128; t += 256) Ws[t] = Wi[t];
    __syncthreads();

    int gid = blockIdx.x * 256 + threadIdx.x;
    int i = gid >> 5, c = gid & 31;
    if (i >= NN) return;

    float xr[7];
#pragma unroll
    for (int k = 0; k < 7; k++) xr[k] = x[i * 7 + k];

    const float4* Ws4 = (const float4*)Ws;
    float4 acc = ((const float4*)bi)[c];
#pragma unroll
    for (int k = 0; k < 7; k++) {
        float4 w = Ws4[k * 32 + c];
        acc.x = fmaf(xr[k], w.x, acc.x);
        acc.y = fmaf(xr[k], w.y, acc.y);
        acc.z = fmaf(xr[k], w.z, acc.z);
        acc.w = fmaf(xr[k], w.w, acc.w);
    }
    acc.x = fmaxf(acc.x, 0.f); acc.y = fmaxf(acc.y, 0.f);
    acc.z = fmaxf(acc.z, 0.f); acc.w = fmaxf(acc.w, 0.f);
    ((float4*)h)[i * 32 + c] = acc;
}

// ---------------- SGEMM: C[N,NCOL] = A[N,128] @ W[128,NCOL] ----------------
template <int NCOL>
__global__ __launch_bounds__(256) void k_gemm(
    const float* __restrict__ A, const float* __restrict__ W, float* __restrict__ C)
{
    constexpr int TN = NCOL / 16;      // 8 (NCOL=128) or 4 (NCOL=64)
    __shared__ float As[128][33];
    __shared__ __align__(16) float Bs[32][NCOL];

    int tid = threadIdx.x;
    int tx = tid & 15, ty = tid >> 4;
    int m0 = blockIdx.x * 128;

    float acc[8][TN];
#pragma unroll
    for (int i = 0; i < 8; i++)
#pragma unroll
        for (int j = 0; j < TN; j++) acc[i][j] = 0.f;

    for (int k0 = 0; k0 < 128; k0 += 32) {
        // A tile: 128 rows x 32 k, scalar stores into padded [128][33]
#pragma unroll
        for (int p = 0; p < 4; p++) {
            int f = tid + p * 256;
            int row = f >> 3, kq = f & 7;
            int gr = m0 + row;
            float4 v = (gr < NN) ? *(const float4*)(A + gr * 128 + k0 + kq * 4)
                                 : make_float4(0.f, 0.f, 0.f, 0.f);
            As[row][kq * 4 + 0] = v.x;
            As[row][kq * 4 + 1] = v.y;
            As[row][kq * 4 + 2] = v.z;
            As[row][kq * 4 + 3] = v.w;
        }
        // B tile: 32 x NCOL, direct copy
        constexpr int NB4 = (32 * NCOL / 4) / 256;  // 4 or 2
#pragma unroll
        for (int p = 0; p < NB4; p++) {
            int f = tid + p * 256;
            int row = f / (NCOL / 4), cq = f % (NCOL / 4);
            float4 v = *(const float4*)(W + (k0 + row) * NCOL + cq * 4);
            *(float4*)&Bs[row][cq * 4] = v;
        }
        __syncthreads();

#pragma unroll
        for (int kk = 0; kk < 32; kk++) {
            float a[8];
#pragma unroll
            for (int i = 0; i < 4; i++) {
                a[i]     = As[ty * 4 + i][kk];
                a[4 + i] = As[64 + ty * 4 + i][kk];
            }
            float b[TN];
            float4 b0 = *(const float4*)&Bs[kk][tx * 4];
            b[0] = b0.x; b[1] = b0.y; b[2] = b0.z; b[3] = b0.w;
            if constexpr (TN == 8) {
                float4 b1 = *(const float4*)&Bs[kk][64 + tx * 4];
                b[4] = b1.x; b[5] = b1.y; b[6] = b1.z; b[7] = b1.w;
            }
#pragma unroll
            for (int i = 0; i < 8; i++)
#pragma unroll
                for (int j = 0; j < TN; j++)
                    acc[i][j] = fmaf(a[i], b[j], acc[i][j]);
        }
        __syncthreads();
    }

#pragma unroll
    for (int i = 0; i < 8; i++) {
        int gr = m0 + ((i < 4) ? (ty * 4 + i) : (64 + ty * 4 + (i - 4)));
        if (gr < NN) {
            *(float4*)(C + gr * NCOL + tx * 4) =
                make_float4(acc[i][0], acc[i][1], acc[i][2], acc[i][3]);
            if constexpr (TN == 8)
                *(float4*)(C + gr * NCOL + 64 + tx * 4) =
                    make_float4(acc[i][4], acc[i][5], acc[i][6], acc[i][7]);
        }
    }
}

// ---------------- fused conv-agg + bias + BN + relu + residual (width 128) ----------------
__global__ __launch_bounds__(256) void k_agg128(
    const float* __restrict__ lin, const float* __restrict__ resid,
    const float* __restrict__ bias, const float* __restrict__ gam,
    const float* __restrict__ bet, const float* __restrict__ mea,
    const float* __restrict__ var, float* __restrict__ out)
{
    int w = (blockIdx.x * blockDim.x + threadIdx.x) >> 5;
    int lane = threadIdx.x & 31;
    if (w >= NN) return;

    int start = g_rowptr[w], end = g_rowptr[w + 1];
    float di = g_dinv[w];
    const float4* lin4 = (const float4*)lin;

    float4 acc = make_float4(0.f, 0.f, 0.f, 0.f);
    for (int e0 = start; e0 < end; e0 += 32) {
        int idx = e0 + lane;
        int s = 0; float dv = 0.f;
        if (idx < end) { s = g_cols[idx]; dv = g_dinv[s]; }
        int nn = min(32, end - e0);
        for (int j = 0; j < nn; j++) {
            int   sj = __shfl_sync(0xffffffffu, s, j);
            float cj = __shfl_sync(0xffffffffu, dv, j) * di;
            float4 t = lin4[sj * 32 + lane];
            acc.x = fmaf(t.x, cj, acc.x);
            acc.y = fmaf(t.y, cj, acc.y);
            acc.z = fmaf(t.z, cj, acc.z);
            acc.w = fmaf(t.w, cj, acc.w);
        }
    }
    float4 sv = lin4[w * 32 + lane];
    float d2 = di * di;
    float4 bb = ((const float4*)bias)[lane];
    float4 gg = ((const float4*)gam)[lane];
    float4 ee = ((const float4*)bet)[lane];
    float4 mm = ((const float4*)mea)[lane];
    float4 vv = ((const float4*)var)[lane];
    float sx = gg.x * rsqrtf(vv.x + 1e-5f);
    float sy = gg.y * rsqrtf(vv.y + 1e-5f);
    float sz = gg.z * rsqrtf(vv.z + 1e-5f);
    float sw = gg.w * rsqrtf(vv.w + 1e-5f);

    float4 rr = ((const float4*)resid)[w * 32 + lane];
    float4 o;
    o.x = fmaxf((acc.x + sv.x * d2 + bb.x - mm.x) * sx + ee.x, 0.f) + rr.x;
    o.y = fmaxf((acc.y + sv.y * d2 + bb.y - mm.y) * sy + ee.y, 0.f) + rr.y;
    o.z = fmaxf((acc.z + sv.z * d2 + bb.z - mm.z) * sz + ee.z, 0.f) + rr.z;
    o.w = fmaxf((acc.w + sv.w * d2 + bb.w - mm.w) * sw + ee.w, 0.f) + rr.w;
    ((float4*)out)[w * 32 + lane] = o;
}

// ---------------- final layer agg (width 64): conv + bias + BN only ----------------
__global__ __launch_bounds__(256) void k_agg64(
    const float* __restrict__ lin,
    const float* __restrict__ bias, const float* __restrict__ gam,
    const float* __restrict__ bet, const float* __restrict__ mea,
    const float* __restrict__ var, float* __restrict__ out)
{
    int w = (blockIdx.x * blockDim.x + threadIdx.x) >> 5;
    int lane = threadIdx.x & 31;
    if (w >= NN) return;

    int start = g_rowptr[w], end = g_rowptr[w + 1];
    float di = g_dinv[w];
    const float2* lin2 = (const float2*)lin;

    float2 acc = make_float2(0.f, 0.f);
    for (int e0 = start; e0 < end; e0 += 32) {
        int idx = e0 + lane;
        int s = 0; float dv = 0.f;
        if (idx < end) { s = g_cols[idx]; dv = g_dinv[s]; }
        int nn = min(32, end - e0);
        for (int j = 0; j < nn; j++) {
            int   sj = __shfl_sync(0xffffffffu, s, j);
            float cj = __shfl_sync(0xffffffffu, dv, j) * di;
            float2 t = lin2[sj * 32 + lane];
            acc.x = fmaf(t.x, cj, acc.x);
            acc.y = fmaf(t.y, cj, acc.y);
        }
    }
    float2 sv = lin2[w * 32 + lane];
    float d2 = di * di;
    float2 bb = ((const float2*)bias)[lane];
    float2 gg = ((const float2*)gam)[lane];
    float2 ee = ((const float2*)bet)[lane];
    float2 mm = ((const float2*)mea)[lane];
    float2 vv = ((const float2*)var)[lane];
    float sx = gg.x * rsqrtf(vv.x + 1e-5f);
    float sy = gg.y * rsqrtf(vv.y + 1e-5f);

    float2 o;
    o.x = (acc.x + sv.x * d2 + bb.x - mm.x) * sx + ee.x;
    o.y = (acc.y + sv.y * d2 + bb.y - mm.y) * sy + ee.y;
    ((float2*)out)[w * 32 + lane] = o;
}

// ---------------- launch ----------------
extern "C" void kernel_launch(void* const* d_in, const int* in_sizes, int n_in,
                              void* d_out, int out_size)
{
    const float* x    = (const float*)d_in[0];
    const void*  ei   = d_in[1];
    const float* W_in = (const float*)d_in[2];
    const float* b_in = (const float*)d_in[3];
    const float* W0 = (const float*)d_in[4];
    const float* b0 = (const float*)d_in[5];
    const float* g0 = (const float*)d_in[6];
    const float* e0 = (const float*)d_in[7];
    const float* m0 = (const float*)d_in[8];
    const float* v0 = (const float*)d_in[9];
    const float* W1 = (const float*)d_in[10];
    const float* b1 = (const float*)d_in[11];
    const float* g1 = (const float*)d_in[12];
    const float* e1 = (const float*)d_in[13];
    const float* m1 = (const float*)d_in[14];
    const float* v1 = (const float*)d_in[15];
    const float* W2 = (const float*)d_in[16];
    const float* b2 = (const float*)d_in[17];
    const float* g2 = (const float*)d_in[18];
    const float* e2 = (const float*)d_in[19];
    const float* m2 = (const float*)d_in[20];
    const float* v2 = (const float*)d_in[21];
    float* out = (float*)d_out;

    float *bufA, *bufB, *bufC;
    cudaGetSymbolAddress((void**)&bufA, g_bufA);
    cudaGetSymbolAddress((void**)&bufB, g_bufB);
    cudaGetSymbolAddress((void**)&bufC, g_bufC);

    // edge_index dtype detection (int32 vs int64)
    k_detect<<<1, 1>>>((const unsigned int*)ei);

    // CSR build (counting sort by dst) + degrees
    k_zero_cnt<<<(NN + 255) / 256, 256>>>();
    k_hist<<<(EE + 255) / 256, 256>>>(ei);
    k_scan1<<<NBLK, 512>>>();
    k_scan2<<<1, 256>>>();
    k_scan3<<<(NN + 255) / 256, 256>>>();
    k_fill<<<(EE + 255) / 256, 256>>>(ei);

    // h = relu(x @ W_in + b_in)
    k_inproj<<<(NN * 32 + 255) / 256, 256>>>(x, W_in, b_in, bufA);

    // layer 0
    k_gemm<128><<<(NN + 127) / 128, 256>>>(bufA, W0, bufB);
    k_agg128<<<(NN * 32 + 255) / 256, 256>>>(bufB, bufA, b0, g0, e0, m0, v0, bufC);
    // layer 1
    k_gemm<128><<<(NN + 127) / 128, 256>>>(bufC, W1, bufB);
    k_agg128<<<(NN * 32 + 255) / 256, 256>>>(bufB, bufC, b1, g1, e1, m1, v1, bufA);
    // layer 2 (final)
    k_gemm<64><<<(NN + 127) / 128, 256>>>(bufA, W2, bufB);
    k_agg64<<<(NN * 32 + 255) / 256, 256>>>(bufB, b2, g2, e2, m2, v2, out);
}

// round 5
// speedup vs baseline: 1.0724x; 1.0724x over previous
#include <cuda_runtime.h>
#include <cuda_bf16.h>
#include <cstdint>

#define NN 100000
#define EE 3200000
#define NBLK 196   // ceil(NN/512)
#define KK 128
#define KP 136     // padded smem row stride (elems): 272B = 68 words -> conflict-free frags

// ---------------- scratch (device globals; no allocations) ----------------
__device__ float g_bufA[NN * 128];
__device__ float g_bufB[NN * 128];
__device__ float g_bufC[NN * 128];
__device__ float g_dinv[NN];
__device__ int   g_cnt[NN];
__device__ int   g_rowptr[NN + 1];
__device__ int   g_cols[EE];
__device__ int   g_bsum[256];
__device__ int   g_is64;
// split weights, [N][K] layout with stride KP: [0]=W0hi [1]=W0lo [2]=W1hi [3]=W1lo [4]=W2hi [5]=W2lo
__device__ unsigned short g_Wsplit[6][128 * KP];

// ---------------- warp mma helper (baseline PTX, valid on sm_103) ----------------
__device__ __forceinline__ void mma16816(float* c, const uint32_t* a, uint32_t b0, uint32_t b1) {
    asm volatile(
        "mma.sync.aligned.m16n8k16.row.col.f32.bf16.bf16.f32 "
        "{%0,%1,%2,%3}, {%4,%5,%6,%7}, {%8,%9}, {%0,%1,%2,%3};"
        : "+f"(c[0]), "+f"(c[1]), "+f"(c[2]), "+f"(c[3])
        : "r"(a[0]), "r"(a[1]), "r"(a[2]), "r"(a[3]), "r"(b0), "r"(b1));
}

// ---------------- dtype detection for edge_index ----------------
__global__ void k_detect(const unsigned int* __restrict__ ei_raw) {
    unsigned int o = 0;
    for (int i = 0; i < 2048; i++) o |= ei_raw[2 * i + 1];
    g_is64 = (o == 0u) ? 1 : 0;
}
__device__ __forceinline__ int load_edge(const void* ei, long long idx) {
    int v;
    if (g_is64) v = (int)((const long long*)ei)[idx];
    else        v = ((const int*)ei)[idx];
    return min(max(v, 0), NN - 1);
}

// ---------------- CSR build ----------------
__global__ void k_zero_cnt() {
    int i = blockIdx.x * blockDim.x + threadIdx.x;
    if (i < NN) g_cnt[i] = 0;
}
__global__ void k_hist(const void* __restrict__ ei) {
    int e = blockIdx.x * blockDim.x + threadIdx.x;
    if (e < EE) atomicAdd(&g_cnt[load_edge(ei, (long long)EE + e)], 1);
}
__global__ void k_scan1() {
    __shared__ int s[512];
    int t = threadIdx.x;
    int i = blockIdx.x * 512 + t;
    int v = (i < NN) ? g_cnt[i] : 0;
    s[t] = v;
    __syncthreads();
    for (int off = 1; off < 512; off <<= 1) {
        int x = (t >= off) ? s[t - off] : 0;
        __syncthreads();
        s[t] += x;
        __syncthreads();
    }
    if (i < NN) g_rowptr[i] = s[t] - v;
    if (t == 511) g_bsum[blockIdx.x] = s[511];
}
__global__ void k_scan2() {
    __shared__ int s[256];
    int t = threadIdx.x;
    int v = (t < NBLK) ? g_bsum[t] : 0;
    s[t] = v;
    __syncthreads();
    for (int off = 1; off < 256; off <<= 1) {
        int x = (t >= off) ? s[t - off] : 0;
        __syncthreads();
        s[t] += x;
        __syncthreads();
    }
    if (t < NBLK) g_bsum[t] = s[t] - v;
}
__global__ void k_scan3() {
    int i = blockIdx.x * blockDim.x + threadIdx.x;
    if (i < NN) {
        g_rowptr[i] += g_bsum[i >> 9];
        g_dinv[i] = rsqrtf((float)g_cnt[i] + 1.0f);
        g_cnt[i] = 0;
    }
    if (i == 0) g_rowptr[NN] = EE;
}
__global__ void k_fill(const void* __restrict__ ei) {
    int e = blockIdx.x * blockDim.x + threadIdx.x;
    if (e < EE) {
        int d = load_edge(ei, (long long)EE + e);
        int s = load_edge(ei, e);
        int p = atomicAdd(&g_cnt[d], 1);
        g_cols[g_rowptr[d] + p] = s;
    }
}

// ---------------- weight prep: W[K][N] fp32 -> hi/lo bf16 in [N][K] (stride KP) ----------------
__global__ void k_prepW(const float* __restrict__ W, int ncol,
                        unsigned short* __restrict__ bh, unsigned short* __restrict__ bl)
{
    int e = blockIdx.x * blockDim.x + threadIdx.x;
    if (e >= ncol * KK) return;
    int k = e / ncol, n = e % ncol;
    float w = W[e];
    __nv_bfloat16 h = __float2bfloat16(w);
    __nv_bfloat16 l = __float2bfloat16(w - __bfloat162float(h));
    bh[n * KP + k] = *(unsigned short*)&h;
    bl[n * KP + k] = *(unsigned short*)&l;
}

// ---------------- input projection: h = relu(x @ W_in + b_in) ----------------
__global__ __launch_bounds__(256) void k_inproj(
    const float* __restrict__ x, const float* __restrict__ Wi,
    const float* __restrict__ bi, float* __restrict__ h)
{
    __shared__ __align__(16) float Ws[7 * 128];
    for (int t = threadIdx.x; t < 7 * 128; t += 256) Ws[t] = Wi[t];
    __syncthreads();

    int gid = blockIdx.x * 256 + threadIdx.x;
    int i = gid >> 5, c = gid & 31;
    if (i >= NN) return;

    float xr[7];
#pragma unroll
    for (int k = 0; k < 7; k++) xr[k] = x[i * 7 + k];

    const float4* Ws4 = (const float4*)Ws;
    float4 acc = ((const float4*)bi)[c];
#pragma unroll
    for (int k = 0; k < 7; k++) {
        float4 w = Ws4[k * 32 + c];
        acc.x = fmaf(xr[k], w.x, acc.x);
        acc.y = fmaf(xr[k], w.y, acc.y);
        acc.z = fmaf(xr[k], w.z, acc.z);
        acc.w = fmaf(xr[k], w.w, acc.w);
    }
    acc.x = fmaxf(acc.x, 0.f); acc.y = fmaxf(acc.y, 0.f);
    acc.z = fmaxf(acc.z, 0.f); acc.w = fmaxf(acc.w, 0.f);
    ((float4*)h)[i * 32 + c] = acc;
}

// ---------------- tensor-core GEMM via mma.sync: C[N,NCOL] = A[N,128] @ W[128,NCOL] ----------------
// split-bf16, 3 passes accumulated in fp32 registers: Ahi*Bhi + Alo*Bhi + Ahi*Blo.
// smem (ushort elems): A_hi[128*KP], A_lo[128*KP], B_hi[NCOL*KP], B_lo[NCOL*KP]
template <int NCOL>
__global__ __launch_bounds__(256) void k_mma(
    const float* __restrict__ A,
    const unsigned short* __restrict__ BH, const unsigned short* __restrict__ BL,
    float* __restrict__ C)
{
    extern __shared__ unsigned short sm[];
    constexpr int A_HI = 0;
    constexpr int A_LO = 128 * KP;
    constexpr int B_HI = 2 * 128 * KP;
    constexpr int B_LO = 2 * 128 * KP + NCOL * KP;
    constexpr int WN = NCOL / 2;       // warp n-width: 64 or 32
    constexpr int NT = WN / 8;         // n8 tiles per warp: 8 or 4

    int tid = threadIdx.x;
    int wid = tid >> 5, lane = tid & 31;
    int g = lane >> 2, t = lane & 3;
    int wm = wid & 3, wn = wid >> 2;
    int m0 = blockIdx.x * 128;

    // ---- stage A: fp32 -> hi/lo bf16, padded smem ----
#pragma unroll 4
    for (int j = 0; j < 16; j++) {
        int i = tid + j * 256;            // over 128 rows x 32 float4
        int m = i >> 5, k4 = i & 31, k = k4 << 2;
        int row = min(m0 + m, NN - 1);
        float4 a = ((const float4*)A)[(size_t)row * 32 + k4];
        __nv_bfloat16 h0 = __float2bfloat16(a.x), h1 = __float2bfloat16(a.y);
        __nv_bfloat16 h2 = __float2bfloat16(a.z), h3 = __float2bfloat16(a.w);
        __nv_bfloat16 l0 = __float2bfloat16(a.x - __bfloat162float(h0));
        __nv_bfloat16 l1 = __float2bfloat16(a.y - __bfloat162float(h1));
        __nv_bfloat16 l2 = __float2bfloat16(a.z - __bfloat162float(h2));
        __nv_bfloat16 l3 = __float2bfloat16(a.w - __bfloat162float(h3));
        uint32_t h01 = ((uint32_t)*(unsigned short*)&h1 << 16) | *(unsigned short*)&h0;
        uint32_t h23 = ((uint32_t)*(unsigned short*)&h3 << 16) | *(unsigned short*)&h2;
        uint32_t l01 = ((uint32_t)*(unsigned short*)&l1 << 16) | *(unsigned short*)&l0;
        uint32_t l23 = ((uint32_t)*(unsigned short*)&l3 << 16) | *(unsigned short*)&l2;
        *(uint2*)&sm[A_HI + m * KP + k] = make_uint2(h01, h23);
        *(uint2*)&sm[A_LO + m * KP + k] = make_uint2(l01, l23);
    }
    // ---- stage B: raw copy (global layout == smem layout) ----
    {
        constexpr int CNT = NCOL * KP / 8;   // uint4s per array
        const uint4* gh = (const uint4*)BH;
        const uint4* gl = (const uint4*)BL;
        uint4* shh = (uint4*)&sm[B_HI];
        uint4* sll = (uint4*)&sm[B_LO];
        for (int i = tid; i < CNT; i += 256) { shh[i] = gh[i]; sll[i] = gl[i]; }
    }
    __syncthreads();

    float acc[2][NT][4];
#pragma unroll
    for (int mt = 0; mt < 2; mt++)
#pragma unroll
        for (int nt = 0; nt < NT; nt++)
#pragma unroll
            for (int q = 0; q < 4; q++) acc[mt][nt][q] = 0.f;

#pragma unroll
    for (int pass = 0; pass < 3; pass++) {
        const unsigned short* aS = sm + ((pass == 1) ? A_LO : A_HI);
        const unsigned short* bS = sm + ((pass == 2) ? B_LO : B_HI);
        int am = wm * 32;
#pragma unroll
        for (int k0 = 0; k0 < 128; k0 += 16) {
            uint32_t af[2][4];
#pragma unroll
            for (int mt = 0; mt < 2; mt++) {
                int r = am + mt * 16 + g;
                af[mt][0] = *(const uint32_t*)(aS + r * KP + k0 + t * 2);
                af[mt][1] = *(const uint32_t*)(aS + (r + 8) * KP + k0 + t * 2);
                af[mt][2] = *(const uint32_t*)(aS + r * KP + k0 + 8 + t * 2);
                af[mt][3] = *(const uint32_t*)(aS + (r + 8) * KP + k0 + 8 + t * 2);
            }
#pragma unroll
            for (int nt = 0; nt < NT; nt++) {
                int n = wn * WN + nt * 8 + g;
                uint32_t b0 = *(const uint32_t*)(bS + n * KP + k0 + t * 2);
                uint32_t b1 = *(const uint32_t*)(bS + n * KP + k0 + 8 + t * 2);
                mma16816(acc[0][nt], af[0], b0, b1);
                mma16816(acc[1][nt], af[1], b0, b1);
            }
        }
    }

    // ---- epilogue: direct float2 stores ----
#pragma unroll
    for (int mt = 0; mt < 2; mt++) {
        int r0 = m0 + wm * 32 + mt * 16 + g;
        int r1 = r0 + 8;
#pragma unroll
        for (int nt = 0; nt < NT; nt++) {
            int c = wn * WN + nt * 8 + t * 2;
            if (r0 < NN)
                *(float2*)&C[(size_t)r0 * NCOL + c] = make_float2(acc[mt][nt][0], acc[mt][nt][1]);
            if (r1 < NN)
                *(float2*)&C[(size_t)r1 * NCOL + c] = make_float2(acc[mt][nt][2], acc[mt][nt][3]);
        }
    }
}

// ---------------- fused conv-agg + bias + BN + relu + residual (width 128) ----------------
__global__ __launch_bounds__(256) void k_agg128(
    const float* __restrict__ lin, const float* __restrict__ resid,
    const float* __restrict__ bias, const float* __restrict__ gam,
    const float* __restrict__ bet, const float* __restrict__ mea,
    const float* __restrict__ var, float* __restrict__ out)
{
    int w = (blockIdx.x * blockDim.x + threadIdx.x) >> 5;
    int lane = threadIdx.x & 31;
    if (w >= NN) return;

    int start = g_rowptr[w], end = g_rowptr[w + 1];
    float di = g_dinv[w];
    const float4* lin4 = (const float4*)lin;

    float4 acc = make_float4(0.f, 0.f, 0.f, 0.f);
    for (int e0 = start; e0 < end; e0 += 32) {
        int idx = e0 + lane;
        int s = 0; float dv = 0.f;
        if (idx < end) { s = g_cols[idx]; dv = g_dinv[s]; }
        int nn = min(32, end - e0);
        for (int j = 0; j < nn; j++) {
            int   sj = __shfl_sync(0xffffffffu, s, j);
            float cj = __shfl_sync(0xffffffffu, dv, j) * di;
            float4 t = lin4[sj * 32 + lane];
            acc.x = fmaf(t.x, cj, acc.x);
            acc.y = fmaf(t.y, cj, acc.y);
            acc.z = fmaf(t.z, cj, acc.z);
            acc.w = fmaf(t.w, cj, acc.w);
        }
    }
    float4 sv = lin4[w * 32 + lane];
    float d2 = di * di;
    float4 bb = ((const float4*)bias)[lane];
    float4 gg = ((const float4*)gam)[lane];
    float4 ee = ((const float4*)bet)[lane];
    float4 mm = ((const float4*)mea)[lane];
    float4 vv = ((const float4*)var)[lane];
    float sx = gg.x * rsqrtf(vv.x + 1e-5f);
    float sy = gg.y * rsqrtf(vv.y + 1e-5f);
    float sz = gg.z * rsqrtf(vv.z + 1e-5f);
    float sw = gg.w * rsqrtf(vv.w + 1e-5f);

    float4 rr = ((const float4*)resid)[w * 32 + lane];
    float4 o;
    o.x = fmaxf((acc.x + sv.x * d2 + bb.x - mm.x) * sx + ee.x, 0.f) + rr.x;
    o.y = fmaxf((acc.y + sv.y * d2 + bb.y - mm.y) * sy + ee.y, 0.f) + rr.y;
    o.z = fmaxf((acc.z + sv.z * d2 + bb.z - mm.z) * sz + ee.z, 0.f) + rr.z;
    o.w = fmaxf((acc.w + sv.w * d2 + bb.w - mm.w) * sw + ee.w, 0.f) + rr.w;
    ((float4*)out)[w * 32 + lane] = o;
}

// ---------------- final layer agg (width 64): conv + bias + BN only ----------------
__global__ __launch_bounds__(256) void k_agg64(
    const float* __restrict__ lin,
    const float* __restrict__ bias, const float* __restrict__ gam,
    const float* __restrict__ bet, const float* __restrict__ mea,
    const float* __restrict__ var, float* __restrict__ out)
{
    int w = (blockIdx.x * blockDim.x + threadIdx.x) >> 5;
    int lane = threadIdx.x & 31;
    if (w >= NN) return;

    int start = g_rowptr[w], end = g_rowptr[w + 1];
    float di = g_dinv[w];
    const float2* lin2 = (const float2*)lin;

    float2 acc = make_float2(0.f, 0.f);
    for (int e0 = start; e0 < end; e0 += 32) {
        int idx = e0 + lane;
        int s = 0; float dv = 0.f;
        if (idx < end) { s = g_cols[idx]; dv = g_dinv[s]; }
        int nn = min(32, end - e0);
        for (int j = 0; j < nn; j++) {
            int   sj = __shfl_sync(0xffffffffu, s, j);
            float cj = __shfl_sync(0xffffffffu, dv, j) * di;
            float2 t = lin2[sj * 32 + lane];
            acc.x = fmaf(t.x, cj, acc.x);
            acc.y = fmaf(t.y, cj, acc.y);
        }
    }
    float2 sv = lin2[w * 32 + lane];
    float d2 = di * di;
    float2 bb = ((const float2*)bias)[lane];
    float2 gg = ((const float2*)gam)[lane];
    float2 ee = ((const float2*)bet)[lane];
    float2 mm = ((const float2*)mea)[lane];
    float2 vv = ((const float2*)var)[lane];
    float sx = gg.x * rsqrtf(vv.x + 1e-5f);
    float sy = gg.y * rsqrtf(vv.y + 1e-5f);

    float2 o;
    o.x = (acc.x + sv.x * d2 + bb.x - mm.x) * sx + ee.x;
    o.y = (acc.y + sv.y * d2 + bb.y - mm.y) * sy + ee.y;
    ((float2*)out)[w * 32 + lane] = o;
}

// ---------------- launch ----------------
extern "C" void kernel_launch(void* const* d_in, const int* in_sizes, int n_in,
                              void* d_out, int out_size)
{
    const float* x    = (const float*)d_in[0];
    const void*  ei   = d_in[1];
    const float* W_in = (const float*)d_in[2];
    const float* b_in = (const float*)d_in[3];
    const float* W0 = (const float*)d_in[4];
    const float* b0 = (const float*)d_in[5];
    const float* g0 = (const float*)d_in[6];
    const float* e0 = (const float*)d_in[7];
    const float* m0 = (const float*)d_in[8];
    const float* v0 = (const float*)d_in[9];
    const float* W1 = (const float*)d_in[10];
    const float* b1 = (const float*)d_in[11];
    const float* g1 = (const float*)d_in[12];
    const float* e1 = (const float*)d_in[13];
    const float* m1 = (const float*)d_in[14];
    const float* v1 = (const float*)d_in[15];
    const float* W2 = (const float*)d_in[16];
    const float* b2 = (const float*)d_in[17];
    const float* g2 = (const float*)d_in[18];
    const float* e2 = (const float*)d_in[19];
    const float* m2 = (const float*)d_in[20];
    const float* v2 = (const float*)d_in[21];
    float* out = (float*)d_out;

    float *bufA, *bufB, *bufC;
    unsigned short* wsp;
    cudaGetSymbolAddress((void**)&bufA, g_bufA);
    cudaGetSymbolAddress((void**)&bufB, g_bufB);
    cudaGetSymbolAddress((void**)&bufC, g_bufC);
    cudaGetSymbolAddress((void**)&wsp,  g_Wsplit);
    unsigned short* WH0 = wsp + 0 * 128 * KP;
    unsigned short* WL0 = wsp + 1 * 128 * KP;
    unsigned short* WH1 = wsp + 2 * 128 * KP;
    unsigned short* WL1 = wsp + 3 * 128 * KP;
    unsigned short* WH2 = wsp + 4 * 128 * KP;
    unsigned short* WL2 = wsp + 5 * 128 * KP;

    const int SM128 = (2 * 128 * KP + 2 * 128 * KP) * 2;  // 139264 B
    const int SM64  = (2 * 128 * KP + 2 * 64 * KP) * 2;   // 104448 B
    cudaFuncSetAttribute(k_mma<128>, cudaFuncAttributeMaxDynamicSharedMemorySize, SM128);
    cudaFuncSetAttribute(k_mma<64>,  cudaFuncAttributeMaxDynamicSharedMemorySize, SM64);

    // edge_index dtype detection (int32 vs int64)
    k_detect<<<1, 1>>>((const unsigned int*)ei);

    // CSR build (counting sort by dst) + degrees
    k_zero_cnt<<<(NN + 255) / 256, 256>>>();
    k_hist<<<(EE + 255) / 256, 256>>>(ei);
    k_scan1<<<NBLK, 512>>>();
    k_scan2<<<1, 256>>>();
    k_scan3<<<(NN + 255) / 256, 256>>>();
    k_fill<<<(EE + 255) / 256, 256>>>(ei);

    // weight split + relayout
    k_prepW<<<64, 256>>>(W0, 128, WH0, WL0);
    k_prepW<<<64, 256>>>(W1, 128, WH1, WL1);
    k_prepW<<<32, 256>>>(W2, 64,  WH2, WL2);

    // h = relu(x @ W_in + b_in)
    k_inproj<<<(NN * 32 + 255) / 256, 256>>>(x, W_in, b_in, bufA);

    const int GB = (NN + 127) / 128;  // 782
    // layer 0
    k_mma<128><<<GB, 256, SM128>>>(bufA, WH0, WL0, bufB);
    k_agg128<<<(NN * 32 + 255) / 256, 256>>>(bufB, bufA, b0, g0, e0, m0, v0, bufC);
    // layer 1
    k_mma<128><<<GB, 256, SM128>>>(bufC, WH1, WL1, bufB);
    k_agg128<<<(NN * 32 + 255) / 256, 256>>>(bufB, bufC, b1, g1, e1, m1, v1, bufA);
    // layer 2 (final)
    k_mma<64><<<GB, 256, SM64>>>(bufA, WH2, WL2, bufB);
    k_agg64<<<(NN * 32 + 255) / 256, 256>>>(bufB, b2, g2, e2, m2, v2, out);
}

// round 6
// speedup vs baseline: 1.1223x; 1.0466x over previous
#include <cuda_runtime.h>
#include <cuda_bf16.h>
#include <cuda_fp16.h>
#include <cstdint>

#define NN 100000
#define EE 3200000
#define NBLK 196   // ceil(NN/512)
#define KK 128
#define KP 136     // padded smem row stride (elems): 272B = 68 words -> conflict-free frags

// ---------------- scratch (device globals; no allocations) ----------------
__device__ float g_bufA[NN * 128];
__device__ float g_bufB[NN * 128];
__device__ float g_bufC[NN * 128];
__device__ __half g_bufH[NN * 128];   // fp16 shadow of GEMM output (gather operand)
__device__ float g_dinv[NN];
__device__ int   g_cnt[NN];
__device__ int   g_rowptr[NN + 1];
__device__ int   g_cols[EE];
__device__ int   g_bsum[256];
__device__ int   g_is64;
// split weights, [N][K] layout with stride KP
__device__ unsigned short g_Wsplit[6][128 * KP];

// ---------------- warp mma helper (baseline PTX, valid on sm_103) ----------------
__device__ __forceinline__ void mma16816(float* c, const uint32_t* a, uint32_t b0, uint32_t b1) {
    asm volatile(
        "mma.sync.aligned.m16n8k16.row.col.f32.bf16.bf16.f32 "
        "{%0,%1,%2,%3}, {%4,%5,%6,%7}, {%8,%9}, {%0,%1,%2,%3};"
        : "+f"(c[0]), "+f"(c[1]), "+f"(c[2]), "+f"(c[3])
        : "r"(a[0]), "r"(a[1]), "r"(a[2]), "r"(a[3]), "r"(b0), "r"(b1));
}

// ---------------- dtype detection for edge_index ----------------
__global__ void k_detect(const unsigned int* __restrict__ ei_raw) {
    unsigned int o = 0;
    for (int i = 0; i < 2048; i++) o |= ei_raw[2 * i + 1];
    g_is64 = (o == 0u) ? 1 : 0;
}
__device__ __forceinline__ int load_edge(const void* ei, long long idx) {
    int v;
    if (g_is64) v = (int)((const long long*)ei)[idx];
    else        v = ((const int*)ei)[idx];
    return min(max(v, 0), NN - 1);
}

// ---------------- CSR build ----------------
__global__ void k_zero_cnt() {
    int i = blockIdx.x * blockDim.x + threadIdx.x;
    if (i < NN) g_cnt[i] = 0;
}
__global__ void k_hist(const void* __restrict__ ei) {
    int e = blockIdx.x * blockDim.x + threadIdx.x;
    if (e < EE) atomicAdd(&g_cnt[load_edge(ei, (long long)EE + e)], 1);
}
__global__ void k_scan1() {
    __shared__ int s[512];
    int t = threadIdx.x;
    int i = blockIdx.x * 512 + t;
    int v = (i < NN) ? g_cnt[i] : 0;
    s[t] = v;
    __syncthreads();
    for (int off = 1; off < 512; off <<= 1) {
        int x = (t >= off) ? s[t - off] : 0;
        __syncthreads();
        s[t] += x;
        __syncthreads();
    }
    if (i < NN) g_rowptr[i] = s[t] - v;
    if (t == 511) g_bsum[blockIdx.x] = s[511];
}
__global__ void k_scan2() {
    __shared__ int s[256];
    int t = threadIdx.x;
    int v = (t < NBLK) ? g_bsum[t] : 0;
    s[t] = v;
    __syncthreads();
    for (int off = 1; off < 256; off <<= 1) {
        int x = (t >= off) ? s[t - off] : 0;
        __syncthreads();
        s[t] += x;
        __syncthreads();
    }
    if (t < NBLK) g_bsum[t] = s[t] - v;
}
__global__ void k_scan3() {
    int i = blockIdx.x * blockDim.x + threadIdx.x;
    if (i < NN) {
        g_rowptr[i] += g_bsum[i >> 9];
        g_dinv[i] = rsqrtf((float)g_cnt[i] + 1.0f);
        g_cnt[i] = 0;
    }
    if (i == 0) g_rowptr[NN] = EE;
}
__global__ void k_fill(const void* __restrict__ ei) {
    int e = blockIdx.x * blockDim.x + threadIdx.x;
    if (e < EE) {
        int d = load_edge(ei, (long long)EE + e);
        int s = load_edge(ei, e);
        int p = atomicAdd(&g_cnt[d], 1);
        g_cols[g_rowptr[d] + p] = s;
    }
}

// ---------------- weight prep: W[K][N] fp32 -> hi/lo bf16 in [N][K] (stride KP) ----------------
__global__ void k_prepW(const float* __restrict__ W, int ncol,
                        unsigned short* __restrict__ bh, unsigned short* __restrict__ bl)
{
    int e = blockIdx.x * blockDim.x + threadIdx.x;
    if (e >= ncol * KK) return;
    int k = e / ncol, n = e % ncol;
    float w = W[e];
    __nv_bfloat16 h = __float2bfloat16(w);
    __nv_bfloat16 l = __float2bfloat16(w - __bfloat162float(h));
    bh[n * KP + k] = *(unsigned short*)&h;
    bl[n * KP + k] = *(unsigned short*)&l;
}

// ---------------- input projection: h = relu(x @ W_in + b_in) ----------------
__global__ __launch_bounds__(256) void k_inproj(
    const float* __restrict__ x, const float* __restrict__ Wi,
    const float* __restrict__ bi, float* __restrict__ h)
{
    __shared__ __align__(16) float Ws[7 * 128];
    for (int t = threadIdx.x; t < 7 * 128; t += 256) Ws[t] = Wi[t];
    __syncthreads();

    int gid = blockIdx.x * 256 + threadIdx.x;
    int i = gid >> 5, c = gid & 31;
    if (i >= NN) return;

    float xr[7];
#pragma unroll
    for (int k = 0; k < 7; k++) xr[k] = x[i * 7 + k];

    const float4* Ws4 = (const float4*)Ws;
    float4 acc = ((const float4*)bi)[c];
#pragma unroll
    for (int k = 0; k < 7; k++) {
        float4 w = Ws4[k * 32 + c];
        acc.x = fmaf(xr[k], w.x, acc.x);
        acc.y = fmaf(xr[k], w.y, acc.y);
        acc.z = fmaf(xr[k], w.z, acc.z);
        acc.w = fmaf(xr[k], w.w, acc.w);
    }
    acc.x = fmaxf(acc.x, 0.f); acc.y = fmaxf(acc.y, 0.f);
    acc.z = fmaxf(acc.z, 0.f); acc.w = fmaxf(acc.w, 0.f);
    ((float4*)h)[i * 32 + c] = acc;
}

// ---------------- tensor-core GEMM via mma.sync: C = A[N,128] @ W[128,NCOL] ----------------
// split-bf16 3-pass; fp32 out C + fp16 shadow H (gather operand for agg).
template <int NCOL>
__global__ __launch_bounds__(256) void k_mma(
    const float* __restrict__ A,
    const unsigned short* __restrict__ BH, const unsigned short* __restrict__ BL,
    float* __restrict__ C, __half* __restrict__ Hout)
{
    extern __shared__ unsigned short sm[];
    constexpr int A_HI = 0;
    constexpr int A_LO = 128 * KP;
    constexpr int B_HI = 2 * 128 * KP;
    constexpr int B_LO = 2 * 128 * KP + NCOL * KP;
    constexpr int WN = NCOL / 2;
    constexpr int NT = WN / 8;

    int tid = threadIdx.x;
    int wid = tid >> 5, lane = tid & 31;
    int g = lane >> 2, t = lane & 3;
    int wm = wid & 3, wn = wid >> 2;
    int m0 = blockIdx.x * 128;

    // ---- stage A: fp32 -> hi/lo bf16, padded smem ----
#pragma unroll 4
    for (int j = 0; j < 16; j++) {
        int i = tid + j * 256;
        int m = i >> 5, k4 = i & 31, k = k4 << 2;
        int row = min(m0 + m, NN - 1);
        float4 a = ((const float4*)A)[(size_t)row * 32 + k4];
        __nv_bfloat16 h0 = __float2bfloat16(a.x), h1 = __float2bfloat16(a.y);
        __nv_bfloat16 h2 = __float2bfloat16(a.z), h3 = __float2bfloat16(a.w);
        __nv_bfloat16 l0 = __float2bfloat16(a.x - __bfloat162float(h0));
        __nv_bfloat16 l1 = __float2bfloat16(a.y - __bfloat162float(h1));
        __nv_bfloat16 l2 = __float2bfloat16(a.z - __bfloat162float(h2));
        __nv_bfloat16 l3 = __float2bfloat16(a.w - __bfloat162float(h3));
        uint32_t h01 = ((uint32_t)*(unsigned short*)&h1 << 16) | *(unsigned short*)&h0;
        uint32_t h23 = ((uint32_t)*(unsigned short*)&h3 << 16) | *(unsigned short*)&h2;
        uint32_t l01 = ((uint32_t)*(unsigned short*)&l1 << 16) | *(unsigned short*)&l0;
        uint32_t l23 = ((uint32_t)*(unsigned short*)&l3 << 16) | *(unsigned short*)&l2;
        *(uint2*)&sm[A_HI + m * KP + k] = make_uint2(h01, h23);
        *(uint2*)&sm[A_LO + m * KP + k] = make_uint2(l01, l23);
    }
    // ---- stage B: raw copy ----
    {
        constexpr int CNT = NCOL * KP / 8;
        const uint4* gh = (const uint4*)BH;
        const uint4* gl = (const uint4*)BL;
        uint4* shh = (uint4*)&sm[B_HI];
        uint4* sll = (uint4*)&sm[B_LO];
        for (int i = tid; i < CNT; i += 256) { shh[i] = gh[i]; sll[i] = gl[i]; }
    }
    __syncthreads();

    float acc[2][NT][4];
#pragma unroll
    for (int mt = 0; mt < 2; mt++)
#pragma unroll
        for (int nt = 0; nt < NT; nt++)
#pragma unroll
            for (int q = 0; q < 4; q++) acc[mt][nt][q] = 0.f;

#pragma unroll
    for (int pass = 0; pass < 3; pass++) {
        const unsigned short* aS = sm + ((pass == 1) ? A_LO : A_HI);
        const unsigned short* bS = sm + ((pass == 2) ? B_LO : B_HI);
        int am = wm * 32;
#pragma unroll
        for (int k0 = 0; k0 < 128; k0 += 16) {
            uint32_t af[2][4];
#pragma unroll
            for (int mt = 0; mt < 2; mt++) {
                int r = am + mt * 16 + g;
                af[mt][0] = *(const uint32_t*)(aS + r * KP + k0 + t * 2);
                af[mt][1] = *(const uint32_t*)(aS + (r + 8) * KP + k0 + t * 2);
                af[mt][2] = *(const uint32_t*)(aS + r * KP + k0 + 8 + t * 2);
                af[mt][3] = *(const uint32_t*)(aS + (r + 8) * KP + k0 + 8 + t * 2);
            }
#pragma unroll
            for (int nt = 0; nt < NT; nt++) {
                int n = wn * WN + nt * 8 + g;
                uint32_t b0 = *(const uint32_t*)(bS + n * KP + k0 + t * 2);
                uint32_t b1 = *(const uint32_t*)(bS + n * KP + k0 + 8 + t * 2);
                mma16816(acc[0][nt], af[0], b0, b1);
                mma16816(acc[1][nt], af[1], b0, b1);
            }
        }
    }

    // ---- epilogue: fp32 stores + fp16 shadow stores ----
#pragma unroll
    for (int mt = 0; mt < 2; mt++) {
        int r0 = m0 + wm * 32 + mt * 16 + g;
        int r1 = r0 + 8;
#pragma unroll
        for (int nt = 0; nt < NT; nt++) {
            int c = wn * WN + nt * 8 + t * 2;
            if (r0 < NN) {
                *(float2*)&C[(size_t)r0 * NCOL + c] = make_float2(acc[mt][nt][0], acc[mt][nt][1]);
                *(__half2*)&Hout[(size_t)r0 * NCOL + c] =
                    __floats2half2_rn(acc[mt][nt][0], acc[mt][nt][1]);
            }
            if (r1 < NN) {
                *(float2*)&C[(size_t)r1 * NCOL + c] = make_float2(acc[mt][nt][2], acc[mt][nt][3]);
                *(__half2*)&Hout[(size_t)r1 * NCOL + c] =
                    __floats2half2_rn(acc[mt][nt][2], acc[mt][nt][3]);
            }
        }
    }
}

// ---------------- fused agg (fp16 gather) + bias + BN + relu + residual (width 128) ----------------
__global__ __launch_bounds__(256) void k_agg128(
    const float* __restrict__ lin, const __half* __restrict__ linH,
    const float* __restrict__ resid,
    const float* __restrict__ bias, const float* __restrict__ gam,
    const float* __restrict__ bet, const float* __restrict__ mea,
    const float* __restrict__ var, float* __restrict__ out)
{
    int w = (blockIdx.x * blockDim.x + threadIdx.x) >> 5;
    int lane = threadIdx.x & 31;
    if (w >= NN) return;

    int start = g_rowptr[w], end = g_rowptr[w + 1];
    float di = g_dinv[w];
    const uint2* linH2 = (const uint2*)linH;   // 4 halves per lane

    float4 acc = make_float4(0.f, 0.f, 0.f, 0.f);
    for (int e0 = start; e0 < end; e0 += 32) {
        int idx = e0 + lane;
        int s = 0; float dv = 0.f;
        if (idx < end) { s = g_cols[idx]; dv = g_dinv[s]; }
        int nn = min(32, end - e0);
        for (int j = 0; j < nn; j++) {
            int   sj = __shfl_sync(0xffffffffu, s, j);
            float cj = __shfl_sync(0xffffffffu, dv, j) * di;
            uint2 u = linH2[sj * 32 + lane];
            float2 f0 = __half22float2(*(__half2*)&u.x);
            float2 f1 = __half22float2(*(__half2*)&u.y);
            acc.x = fmaf(f0.x, cj, acc.x);
            acc.y = fmaf(f0.y, cj, acc.y);
            acc.z = fmaf(f1.x, cj, acc.z);
            acc.w = fmaf(f1.y, cj, acc.w);
        }
    }
    const float4* lin4 = (const float4*)lin;
    float4 sv = lin4[w * 32 + lane];
    float d2 = di * di;
    float4 bb = ((const float4*)bias)[lane];
    float4 gg = ((const float4*)gam)[lane];
    float4 ee = ((const float4*)bet)[lane];
    float4 mm = ((const float4*)mea)[lane];
    float4 vv = ((const float4*)var)[lane];
    float sx = gg.x * rsqrtf(vv.x + 1e-5f);
    float sy = gg.y * rsqrtf(vv.y + 1e-5f);
    float sz = gg.z * rsqrtf(vv.z + 1e-5f);
    float sw = gg.w * rsqrtf(vv.w + 1e-5f);

    float4 rr = ((const float4*)resid)[w * 32 + lane];
    float4 o;
    o.x = fmaxf((acc.x + sv.x * d2 + bb.x - mm.x) * sx + ee.x, 0.f) + rr.x;
    o.y = fmaxf((acc.y + sv.y * d2 + bb.y - mm.y) * sy + ee.y, 0.f) + rr.y;
    o.z = fmaxf((acc.z + sv.z * d2 + bb.z - mm.z) * sz + ee.z, 0.f) + rr.z;
    o.w = fmaxf((acc.w + sv.w * d2 + bb.w - mm.w) * sw + ee.w, 0.f) + rr.w;
    ((float4*)out)[w * 32 + lane] = o;
}

// ---------------- final layer agg (width 64, fp16 gather): conv + bias + BN only ----------------
__global__ __launch_bounds__(256) void k_agg64(
    const float* __restrict__ lin, const __half* __restrict__ linH,
    const float* __restrict__ bias, const float* __restrict__ gam,
    const float* __restrict__ bet, const float* __restrict__ mea,
    const float* __restrict__ var, float* __restrict__ out)
{
    int w = (blockIdx.x * blockDim.x + threadIdx.x) >> 5;
    int lane = threadIdx.x & 31;
    if (w >= NN) return;

    int start = g_rowptr[w], end = g_rowptr[w + 1];
    float di = g_dinv[w];
    const __half2* linH2 = (const __half2*)linH;   // 2 halves per lane

    float2 acc = make_float2(0.f, 0.f);
    for (int e0 = start; e0 < end; e0 += 32) {
        int idx = e0 + lane;
        int s = 0; float dv = 0.f;
        if (idx < end) { s = g_cols[idx]; dv = g_dinv[s]; }
        int nn = min(32, end - e0);
        for (int j = 0; j < nn; j++) {
            int   sj = __shfl_sync(0xffffffffu, s, j);
            float cj = __shfl_sync(0xffffffffu, dv, j) * di;
            float2 f = __half22float2(linH2[sj * 32 + lane]);
            acc.x = fmaf(f.x, cj, acc.x);
            acc.y = fmaf(f.y, cj, acc.y);
        }
    }
    const float2* lin2 = (const float2*)lin;
    float2 sv = lin2[w * 32 + lane];
    float d2 = di * di;
    float2 bb = ((const float2*)bias)[lane];
    float2 gg = ((const float2*)gam)[lane];
    float2 ee = ((const float2*)bet)[lane];
    float2 mm = ((const float2*)mea)[lane];
    float2 vv = ((const float2*)var)[lane];
    float sx = gg.x * rsqrtf(vv.x + 1e-5f);
    float sy = gg.y * rsqrtf(vv.y + 1e-5f);

    float2 o;
    o.x = (acc.x + sv.x * d2 + bb.x - mm.x) * sx + ee.x;
    o.y = (acc.y + sv.y * d2 + bb.y - mm.y) * sy + ee.y;
    ((float2*)out)[w * 32 + lane] = o;
}

// ---------------- launch ----------------
extern "C" void kernel_launch(void* const* d_in, const int* in_sizes, int n_in,
                              void* d_out, int out_size)
{
    const float* x    = (const float*)d_in[0];
    const void*  ei   = d_in[1];
    const float* W_in = (const float*)d_in[2];
    const float* b_in = (const float*)d_in[3];
    const float* W0 = (const float*)d_in[4];
    const float* b0 = (const float*)d_in[5];
    const float* g0 = (const float*)d_in[6];
    const float* e0 = (const float*)d_in[7];
    const float* m0 = (const float*)d_in[8];
    const float* v0 = (const float*)d_in[9];
    const float* W1 = (const float*)d_in[10];
    const float* b1 = (const float*)d_in[11];
    const float* g1 = (const float*)d_in[12];
    const float* e1 = (const float*)d_in[13];
    const float* m1 = (const float*)d_in[14];
    const float* v1 = (const float*)d_in[15];
    const float* W2 = (const float*)d_in[16];
    const float* b2 = (const float*)d_in[17];
    const float* g2 = (const float*)d_in[18];
    const float* e2 = (const float*)d_in[19];
    const float* m2 = (const float*)d_in[20];
    const float* v2 = (const float*)d_in[21];
    float* out = (float*)d_out;

    float *bufA, *bufB, *bufC;
    __half* bufH;
    unsigned short* wsp;
    cudaGetSymbolAddress((void**)&bufA, g_bufA);
    cudaGetSymbolAddress((void**)&bufB, g_bufB);
    cudaGetSymbolAddress((void**)&bufC, g_bufC);
    cudaGetSymbolAddress((void**)&bufH, g_bufH);
    cudaGetSymbolAddress((void**)&wsp,  g_Wsplit);
    unsigned short* WH0 = wsp + 0 * 128 * KP;
    unsigned short* WL0 = wsp + 1 * 128 * KP;
    unsigned short* WH1 = wsp + 2 * 128 * KP;
    unsigned short* WL1 = wsp + 3 * 128 * KP;
    unsigned short* WH2 = wsp + 4 * 128 * KP;
    unsigned short* WL2 = wsp + 5 * 128 * KP;

    const int SM128 = (2 * 128 * KP + 2 * 128 * KP) * 2;  // 139264 B
    const int SM64  = (2 * 128 * KP + 2 * 64 * KP) * 2;   // 104448 B
    cudaFuncSetAttribute(k_mma<128>, cudaFuncAttributeMaxDynamicSharedMemorySize, SM128);
    cudaFuncSetAttribute(k_mma<64>,  cudaFuncAttributeMaxDynamicSharedMemorySize, SM64);

    // edge_index dtype detection (int32 vs int64)
    k_detect<<<1, 1>>>((const unsigned int*)ei);

    // CSR build (counting sort by dst) + degrees
    k_zero_cnt<<<(NN + 255) / 256, 256>>>();
    k_hist<<<(EE + 255) / 256, 256>>>(ei);
    k_scan1<<<NBLK, 512>>>();
    k_scan2<<<1, 256>>>();
    k_scan3<<<(NN + 255) / 256, 256>>>();
    k_fill<<<(EE + 255) / 256, 256>>>(ei);

    // weight split + relayout
    k_prepW<<<64, 256>>>(W0, 128, WH0, WL0);
    k_prepW<<<64, 256>>>(W1, 128, WH1, WL1);
    k_prepW<<<32, 256>>>(W2, 64,  WH2, WL2);

    // h = relu(x @ W_in + b_in)
    k_inproj<<<(NN * 32 + 255) / 256, 256>>>(x, W_in, b_in, bufA);

    const int GB = (NN + 127) / 128;  // 782
    // layer 0
    k_mma<128><<<GB, 256, SM128>>>(bufA, WH0, WL0, bufB, bufH);
    k_agg128<<<(NN * 32 + 255) / 256, 256>>>(bufB, bufH, bufA, b0, g0, e0, m0, v0, bufC);
    // layer 1
    k_mma<128><<<GB, 256, SM128>>>(bufC, WH1, WL1, bufB, bufH);
    k_agg128<<<(NN * 32 + 255) / 256, 256>>>(bufB, bufH, bufC, b1, g1, e1, m1, v1, bufA);
    // layer 2 (final)
    k_mma<64><<<GB, 256, SM64>>>(bufA, WH2, WL2, bufB, bufH);
    k_agg64<<<(NN * 32 + 255) / 256, 256>>>(bufB, bufH, b2, g2, e2, m2, v2, out);
}

// round 7
// speedup vs baseline: 1.1259x; 1.0032x over previous
#include <cuda_runtime.h>
#include <cuda_bf16.h>
#include <cuda_fp16.h>
#include <cstdint>

#define NN 100000
#define EE 3200000
#define NBLK 196   // ceil(NN/512)
#define KK 128
#define KP 136     // padded smem row stride (elems): 272B = 68 words -> conflict-free frags

// ---------------- scratch (device globals; no allocations) ----------------
__device__ float g_bufA[NN * 128];
__device__ float g_bufB[NN * 128];
__device__ float g_bufC[NN * 128];
__device__ __half g_bufH[NN * 128];   // fp16 shadow of GEMM output (gather operand)
__device__ float g_dinv[NN];
__device__ int   g_cnt[NN];
__device__ int   g_rowptr[NN + 1];
__device__ int   g_cols[EE];
__device__ int   g_bsum[256];
__device__ int   g_is64;
// split weights, [N][K] layout with stride KP
__device__ unsigned short g_Wsplit[6][128 * KP];

// ---------------- warp mma helper (baseline PTX, valid on sm_103) ----------------
__device__ __forceinline__ void mma16816(float* c, const uint32_t* a, uint32_t b0, uint32_t b1) {
    asm volatile(
        "mma.sync.aligned.m16n8k16.row.col.f32.bf16.bf16.f32 "
        "{%0,%1,%2,%3}, {%4,%5,%6,%7}, {%8,%9}, {%0,%1,%2,%3};"
        : "+f"(c[0]), "+f"(c[1]), "+f"(c[2]), "+f"(c[3])
        : "r"(a[0]), "r"(a[1]), "r"(a[2]), "r"(a[3]), "r"(b0), "r"(b1));
}

// ---------------- dtype detection for edge_index ----------------
__global__ void k_detect(const unsigned int* __restrict__ ei_raw) {
    unsigned int o = 0;
    for (int i = 0; i < 2048; i++) o |= ei_raw[2 * i + 1];
    g_is64 = (o == 0u) ? 1 : 0;
}
__device__ __forceinline__ int load_edge(const void* ei, long long idx) {
    int v;
    if (g_is64) v = (int)((const long long*)ei)[idx];
    else        v = ((const int*)ei)[idx];
    return min(max(v, 0), NN - 1);
}

// ---------------- CSR build ----------------
__global__ void k_zero_cnt() {
    int i = blockIdx.x * blockDim.x + threadIdx.x;
    if (i < NN) g_cnt[i] = 0;
}
__global__ void k_hist(const void* __restrict__ ei) {
    int e = blockIdx.x * blockDim.x + threadIdx.x;
    if (e < EE) atomicAdd(&g_cnt[load_edge(ei, (long long)EE + e)], 1);
}
__global__ void k_scan1() {
    __shared__ int s[512];
    int t = threadIdx.x;
    int i = blockIdx.x * 512 + t;
    int v = (i < NN) ? g_cnt[i] : 0;
    s[t] = v;
    __syncthreads();
    for (int off = 1; off < 512; off <<= 1) {
        int x = (t >= off) ? s[t - off] : 0;
        __syncthreads();
        s[t] += x;
        __syncthreads();
    }
    if (i < NN) g_rowptr[i] = s[t] - v;
    if (t == 511) g_bsum[blockIdx.x] = s[511];
}
__global__ void k_scan2() {
    __shared__ int s[256];
    int t = threadIdx.x;
    int v = (t < NBLK) ? g_bsum[t] : 0;
    s[t] = v;
    __syncthreads();
    for (int off = 1; off < 256; off <<= 1) {
        int x = (t >= off) ? s[t - off] : 0;
        __syncthreads();
        s[t] += x;
        __syncthreads();
    }
    if (t < NBLK) g_bsum[t] = s[t] - v;
}
__global__ void k_scan3() {
    int i = blockIdx.x * blockDim.x + threadIdx.x;
    if (i < NN) {
        g_rowptr[i] += g_bsum[i >> 9];
        g_dinv[i] = rsqrtf((float)g_cnt[i] + 1.0f);
        g_cnt[i] = 0;
    }
    if (i == 0) g_rowptr[NN] = EE;
}
__global__ void k_fill(const void* __restrict__ ei) {
    int e = blockIdx.x * blockDim.x + threadIdx.x;
    if (e < EE) {
        int d = load_edge(ei, (long long)EE + e);
        int s = load_edge(ei, e);
        int p = atomicAdd(&g_cnt[d], 1);
        g_cols[g_rowptr[d] + p] = s;
    }
}

// ---------------- weight prep: W[K][N] fp32 -> hi/lo bf16 in [N][K] (stride KP) ----------------
__global__ void k_prepW(const float* __restrict__ W, int ncol,
                        unsigned short* __restrict__ bh, unsigned short* __restrict__ bl)
{
    int e = blockIdx.x * blockDim.x + threadIdx.x;
    if (e >= ncol * KK) return;
    int k = e / ncol, n = e % ncol;
    float w = W[e];
    __nv_bfloat16 h = __float2bfloat16(w);
    __nv_bfloat16 l = __float2bfloat16(w - __bfloat162float(h));
    bh[n * KP + k] = *(unsigned short*)&h;
    bl[n * KP + k] = *(unsigned short*)&l;
}

// ---------------- input projection: h = relu(x @ W_in + b_in) ----------------
__global__ __launch_bounds__(256) void k_inproj(
    const float* __restrict__ x, const float* __restrict__ Wi,
    const float* __restrict__ bi, float* __restrict__ h)
{
    __shared__ __align__(16) float Ws[7 * 128];
    for (int t = threadIdx.x; t < 7 * 128; t += 256) Ws[t] = Wi[t];
    __syncthreads();

    int gid = blockIdx.x * 256 + threadIdx.x;
    int i = gid >> 5, c = gid & 31;
    if (i >= NN) return;

    float xr[7];
#pragma unroll
    for (int k = 0; k < 7; k++) xr[k] = x[i * 7 + k];

    const float4* Ws4 = (const float4*)Ws;
    float4 acc = ((const float4*)bi)[c];
#pragma unroll
    for (int k = 0; k < 7; k++) {
        float4 w = Ws4[k * 32 + c];
        acc.x = fmaf(xr[k], w.x, acc.x);
        acc.y = fmaf(xr[k], w.y, acc.y);
        acc.z = fmaf(xr[k], w.z, acc.z);
        acc.w = fmaf(xr[k], w.w, acc.w);
    }
    acc.x = fmaxf(acc.x, 0.f); acc.y = fmaxf(acc.y, 0.f);
    acc.z = fmaxf(acc.z, 0.f); acc.w = fmaxf(acc.w, 0.f);
    ((float4*)h)[i * 32 + c] = acc;
}

// ---------------- tensor-core GEMM via mma.sync: C = A[N,128] @ W[128,NCOL] ----------------
template <int NCOL>
__global__ __launch_bounds__(256) void k_mma(
    const float* __restrict__ A,
    const unsigned short* __restrict__ BH, const unsigned short* __restrict__ BL,
    float* __restrict__ C, __half* __restrict__ Hout)
{
    extern __shared__ unsigned short sm[];
    constexpr int A_HI = 0;
    constexpr int A_LO = 128 * KP;
    constexpr int B_HI = 2 * 128 * KP;
    constexpr int B_LO = 2 * 128 * KP + NCOL * KP;
    constexpr int WN = NCOL / 2;
    constexpr int NT = WN / 8;

    int tid = threadIdx.x;
    int wid = tid >> 5, lane = tid & 31;
    int g = lane >> 2, t = lane & 3;
    int wm = wid & 3, wn = wid >> 2;
    int m0 = blockIdx.x * 128;

    // ---- stage A: fp32 -> hi/lo bf16, padded smem ----
#pragma unroll 4
    for (int j = 0; j < 16; j++) {
        int i = tid + j * 256;
        int m = i >> 5, k4 = i & 31, k = k4 << 2;
        int row = min(m0 + m, NN - 1);
        float4 a = ((const float4*)A)[(size_t)row * 32 + k4];
        __nv_bfloat16 h0 = __float2bfloat16(a.x), h1 = __float2bfloat16(a.y);
        __nv_bfloat16 h2 = __float2bfloat16(a.z), h3 = __float2bfloat16(a.w);
        __nv_bfloat16 l0 = __float2bfloat16(a.x - __bfloat162float(h0));
        __nv_bfloat16 l1 = __float2bfloat16(a.y - __bfloat162float(h1));
        __nv_bfloat16 l2 = __float2bfloat16(a.z - __bfloat162float(h2));
        __nv_bfloat16 l3 = __float2bfloat16(a.w - __bfloat162float(h3));
        uint32_t h01 = ((uint32_t)*(unsigned short*)&h1 << 16) | *(unsigned short*)&h0;
        uint32_t h23 = ((uint32_t)*(unsigned short*)&h3 << 16) | *(unsigned short*)&h2;
        uint32_t l01 = ((uint32_t)*(unsigned short*)&l1 << 16) | *(unsigned short*)&l0;
        uint32_t l23 = ((uint32_t)*(unsigned short*)&l3 << 16) | *(unsigned short*)&l2;
        *(uint2*)&sm[A_HI + m * KP + k] = make_uint2(h01, h23);
        *(uint2*)&sm[A_LO + m * KP + k] = make_uint2(l01, l23);
    }
    // ---- stage B: raw copy ----
    {
        constexpr int CNT = NCOL * KP / 8;
        const uint4* gh = (const uint4*)BH;
        const uint4* gl = (const uint4*)BL;
        uint4* shh = (uint4*)&sm[B_HI];
        uint4* sll = (uint4*)&sm[B_LO];
        for (int i = tid; i < CNT; i += 256) { shh[i] = gh[i]; sll[i] = gl[i]; }
    }
    __syncthreads();

    float acc[2][NT][4];
#pragma unroll
    for (int mt = 0; mt < 2; mt++)
#pragma unroll
        for (int nt = 0; nt < NT; nt++)
#pragma unroll
            for (int q = 0; q < 4; q++) acc[mt][nt][q] = 0.f;

#pragma unroll
    for (int pass = 0; pass < 3; pass++) {
        const unsigned short* aS = sm + ((pass == 1) ? A_LO : A_HI);
        const unsigned short* bS = sm + ((pass == 2) ? B_LO : B_HI);
        int am = wm * 32;
#pragma unroll
        for (int k0 = 0; k0 < 128; k0 += 16) {
            uint32_t af[2][4];
#pragma unroll
            for (int mt = 0; mt < 2; mt++) {
                int r = am + mt * 16 + g;
                af[mt][0] = *(const uint32_t*)(aS + r * KP + k0 + t * 2);
                af[mt][1] = *(const uint32_t*)(aS + (r + 8) * KP + k0 + t * 2);
                af[mt][2] = *(const uint32_t*)(aS + r * KP + k0 + 8 + t * 2);
                af[mt][3] = *(const uint32_t*)(aS + (r + 8) * KP + k0 + 8 + t * 2);
            }
#pragma unroll
            for (int nt = 0; nt < NT; nt++) {
                int n = wn * WN + nt * 8 + g;
                uint32_t b0 = *(const uint32_t*)(bS + n * KP + k0 + t * 2);
                uint32_t b1 = *(const uint32_t*)(bS + n * KP + k0 + 8 + t * 2);
                mma16816(acc[0][nt], af[0], b0, b1);
                mma16816(acc[1][nt], af[1], b0, b1);
            }
        }
    }

    // ---- epilogue: fp32 stores + fp16 shadow stores ----
#pragma unroll
    for (int mt = 0; mt < 2; mt++) {
        int r0 = m0 + wm * 32 + mt * 16 + g;
        int r1 = r0 + 8;
#pragma unroll
        for (int nt = 0; nt < NT; nt++) {
            int c = wn * WN + nt * 8 + t * 2;
            if (r0 < NN) {
                *(float2*)&C[(size_t)r0 * NCOL + c] = make_float2(acc[mt][nt][0], acc[mt][nt][1]);
                *(__half2*)&Hout[(size_t)r0 * NCOL + c] =
                    __floats2half2_rn(acc[mt][nt][0], acc[mt][nt][1]);
            }
            if (r1 < NN) {
                *(float2*)&C[(size_t)r1 * NCOL + c] = make_float2(acc[mt][nt][2], acc[mt][nt][3]);
                *(__half2*)&Hout[(size_t)r1 * NCOL + c] =
                    __floats2half2_rn(acc[mt][nt][2], acc[mt][nt][3]);
            }
        }
    }
}

// ---------------- fused agg (fp16 gather, MLP-4) + bias + BN + relu + residual (width 128) ----------------
__global__ __launch_bounds__(256) void k_agg128(
    const float* __restrict__ lin, const __half* __restrict__ linH,
    const float* __restrict__ resid,
    const float* __restrict__ bias, const float* __restrict__ gam,
    const float* __restrict__ bet, const float* __restrict__ mea,
    const float* __restrict__ var, float* __restrict__ out)
{
    __shared__ int2 s_e[8][32];
    int ws = threadIdx.x >> 5;
    int w = (blockIdx.x * blockDim.x + threadIdx.x) >> 5;
    int lane = threadIdx.x & 31;
    if (w >= NN) return;

    int start = g_rowptr[w], end = g_rowptr[w + 1];
    float di = g_dinv[w];
    const uint2* linH2 = (const uint2*)linH;   // 4 halves per lane

    float4 acc = make_float4(0.f, 0.f, 0.f, 0.f);
    for (int e0 = start; e0 < end; e0 += 32) {
        int idx = e0 + lane;
        if (idx < end) {
            int s = g_cols[idx];
            s_e[ws][lane] = make_int2(s, __float_as_int(g_dinv[s] * di));
        }
        __syncwarp();
        int nn = min(32, end - e0);
        int j = 0;
#pragma unroll 1
        for (; j + 4 <= nn; j += 4) {
            int2 p0 = s_e[ws][j + 0];
            int2 p1 = s_e[ws][j + 1];
            int2 p2 = s_e[ws][j + 2];
            int2 p3 = s_e[ws][j + 3];
            uint2 u0 = linH2[p0.x * 32 + lane];
            uint2 u1 = linH2[p1.x * 32 + lane];
            uint2 u2 = linH2[p2.x * 32 + lane];
            uint2 u3 = linH2[p3.x * 32 + lane];
            float c0 = __int_as_float(p0.y), c1 = __int_as_float(p1.y);
            float c2 = __int_as_float(p2.y), c3 = __int_as_float(p3.y);
            float2 a0 = __half22float2(*(__half2*)&u0.x), b0 = __half22float2(*(__half2*)&u0.y);
            float2 a1 = __half22float2(*(__half2*)&u1.x), b1 = __half22float2(*(__half2*)&u1.y);
            float2 a2 = __half22float2(*(__half2*)&u2.x), b2 = __half22float2(*(__half2*)&u2.y);
            float2 a3 = __half22float2(*(__half2*)&u3.x), b3 = __half22float2(*(__half2*)&u3.y);
            acc.x = fmaf(a0.x, c0, acc.x); acc.y = fmaf(a0.y, c0, acc.y);
            acc.z = fmaf(b0.x, c0, acc.z); acc.w = fmaf(b0.y, c0, acc.w);
            acc.x = fmaf(a1.x, c1, acc.x); acc.y = fmaf(a1.y, c1, acc.y);
            acc.z = fmaf(b1.x, c1, acc.z); acc.w = fmaf(b1.y, c1, acc.w);
            acc.x = fmaf(a2.x, c2, acc.x); acc.y = fmaf(a2.y, c2, acc.y);
            acc.z = fmaf(b2.x, c2, acc.z); acc.w = fmaf(b2.y, c2, acc.w);
            acc.x = fmaf(a3.x, c3, acc.x); acc.y = fmaf(a3.y, c3, acc.y);
            acc.z = fmaf(b3.x, c3, acc.z); acc.w = fmaf(b3.y, c3, acc.w);
        }
        for (; j < nn; j++) {
            int2 p = s_e[ws][j];
            uint2 u = linH2[p.x * 32 + lane];
            float c = __int_as_float(p.y);
            float2 a = __half22float2(*(__half2*)&u.x);
            float2 b = __half22float2(*(__half2*)&u.y);
            acc.x = fmaf(a.x, c, acc.x); acc.y = fmaf(a.y, c, acc.y);
            acc.z = fmaf(b.x, c, acc.z); acc.w = fmaf(b.y, c, acc.w);
        }
        __syncwarp();
    }
    const float4* lin4 = (const float4*)lin;
    float4 sv = lin4[w * 32 + lane];
    float d2 = di * di;
    float4 bb = ((const float4*)bias)[lane];
    float4 gg = ((const float4*)gam)[lane];
    float4 ee = ((const float4*)bet)[lane];
    float4 mm = ((const float4*)mea)[lane];
    float4 vv = ((const float4*)var)[lane];
    float sx = gg.x * rsqrtf(vv.x + 1e-5f);
    float sy = gg.y * rsqrtf(vv.y + 1e-5f);
    float sz = gg.z * rsqrtf(vv.z + 1e-5f);
    float sw = gg.w * rsqrtf(vv.w + 1e-5f);

    float4 rr = ((const float4*)resid)[w * 32 + lane];
    float4 o;
    o.x = fmaxf((acc.x + sv.x * d2 + bb.x - mm.x) * sx + ee.x, 0.f) + rr.x;
    o.y = fmaxf((acc.y + sv.y * d2 + bb.y - mm.y) * sy + ee.y, 0.f) + rr.y;
    o.z = fmaxf((acc.z + sv.z * d2 + bb.z - mm.z) * sz + ee.z, 0.f) + rr.z;
    o.w = fmaxf((acc.w + sv.w * d2 + bb.w - mm.w) * sw + ee.w, 0.f) + rr.w;
    ((float4*)out)[w * 32 + lane] = o;
}

// ---------------- final layer agg (width 64, fp16 gather, MLP-4): conv + bias + BN only ----------------
__global__ __launch_bounds__(256) void k_agg64(
    const float* __restrict__ lin, const __half* __restrict__ linH,
    const float* __restrict__ bias, const float* __restrict__ gam,
    const float* __restrict__ bet, const float* __restrict__ mea,
    const float* __restrict__ var, float* __restrict__ out)
{
    __shared__ int2 s_e[8][32];
    int ws = threadIdx.x >> 5;
    int w = (blockIdx.x * blockDim.x + threadIdx.x) >> 5;
    int lane = threadIdx.x & 31;
    if (w >= NN) return;

    int start = g_rowptr[w], end = g_rowptr[w + 1];
    float di = g_dinv[w];
    const __half2* linH2 = (const __half2*)linH;   // 2 halves per lane

    float2 acc = make_float2(0.f, 0.f);
    for (int e0 = start; e0 < end; e0 += 32) {
        int idx = e0 + lane;
        if (idx < end) {
            int s = g_cols[idx];
            s_e[ws][lane] = make_int2(s, __float_as_int(g_dinv[s] * di));
        }
        __syncwarp();
        int nn = min(32, end - e0);
        int j = 0;
#pragma unroll 1
        for (; j + 4 <= nn; j += 4) {
            int2 p0 = s_e[ws][j + 0];
            int2 p1 = s_e[ws][j + 1];
            int2 p2 = s_e[ws][j + 2];
            int2 p3 = s_e[ws][j + 3];
            __half2 u0 = linH2[p0.x * 32 + lane];
            __half2 u1 = linH2[p1.x * 32 + lane];
            __half2 u2 = linH2[p2.x * 32 + lane];
            __half2 u3 = linH2[p3.x * 32 + lane];
            float2 f0 = __half22float2(u0), f1 = __half22float2(u1);
            float2 f2 = __half22float2(u2), f3 = __half22float2(u3);
            float c0 = __int_as_float(p0.y), c1 = __int_as_float(p1.y);
            float c2 = __int_as_float(p2.y), c3 = __int_as_float(p3.y);
            acc.x = fmaf(f0.x, c0, acc.x); acc.y = fmaf(f0.y, c0, acc.y);
            acc.x = fmaf(f1.x, c1, acc.x); acc.y = fmaf(f1.y, c1, acc.y);
            acc.x = fmaf(f2.x, c2, acc.x); acc.y = fmaf(f2.y, c2, acc.y);
            acc.x = fmaf(f3.x, c3, acc.x); acc.y = fmaf(f3.y, c3, acc.y);
        }
        for (; j < nn; j++) {
            int2 p = s_e[ws][j];
            float2 f = __half22float2(linH2[p.x * 32 + lane]);
            float c = __int_as_float(p.y);
            acc.x = fmaf(f.x, c, acc.x); acc.y = fmaf(f.y, c, acc.y);
        }
        __syncwarp();
    }
    const float2* lin2 = (const float2*)lin;
    float2 sv = lin2[w * 32 + lane];
    float d2 = di * di;
    float2 bb = ((const float2*)bias)[lane];
    float2 gg = ((const float2*)gam)[lane];
    float2 ee = ((const float2*)bet)[lane];
    float2 mm = ((const float2*)mea)[lane];
    float2 vv = ((const float2*)var)[lane];
    float sx = gg.x * rsqrtf(vv.x + 1e-5f);
    float sy = gg.y * rsqrtf(vv.y + 1e-5f);

    float2 o;
    o.x = (acc.x + sv.x * d2 + bb.x - mm.x) * sx + ee.x;
    o.y = (acc.y + sv.y * d2 + bb.y - mm.y) * sy + ee.y;
    ((float2*)out)[w * 32 + lane] = o;
}

// ---------------- launch ----------------
extern "C" void kernel_launch(void* const* d_in, const int* in_sizes, int n_in,
                              void* d_out, int out_size)
{
    const float* x    = (const float*)d_in[0];
    const void*  ei   = d_in[1];
    const float* W_in = (const float*)d_in[2];
    const float* b_in = (const float*)d_in[3];
    const float* W0 = (const float*)d_in[4];
    const float* b0 = (const float*)d_in[5];
    const float* g0 = (const float*)d_in[6];
    const float* e0 = (const float*)d_in[7];
    const float* m0 = (const float*)d_in[8];
    const float* v0 = (const float*)d_in[9];
    const float* W1 = (const float*)d_in[10];
    const float* b1 = (const float*)d_in[11];
    const float* g1 = (const float*)d_in[12];
    const float* e1 = (const float*)d_in[13];
    const float* m1 = (const float*)d_in[14];
    const float* v1 = (const float*)d_in[15];
    const float* W2 = (const float*)d_in[16];
    const float* b2 = (const float*)d_in[17];
    const float* g2 = (const float*)d_in[18];
    const float* e2 = (const float*)d_in[19];
    const float* m2 = (const float*)d_in[20];
    const float* v2 = (const float*)d_in[21];
    float* out = (float*)d_out;

    float *bufA, *bufB, *bufC;
    __half* bufH;
    unsigned short* wsp;
    cudaGetSymbolAddress((void**)&bufA, g_bufA);
    cudaGetSymbolAddress((void**)&bufB, g_bufB);
    cudaGetSymbolAddress((void**)&bufC, g_bufC);
    cudaGetSymbolAddress((void**)&bufH, g_bufH);
    cudaGetSymbolAddress((void**)&wsp,  g_Wsplit);
    unsigned short* WH0 = wsp + 0 * 128 * KP;
    unsigned short* WL0 = wsp + 1 * 128 * KP;
    unsigned short* WH1 = wsp + 2 * 128 * KP;
    unsigned short* WL1 = wsp + 3 * 128 * KP;
    unsigned short* WH2 = wsp + 4 * 128 * KP;
    unsigned short* WL2 = wsp + 5 * 128 * KP;

    const int SM128 = (2 * 128 * KP + 2 * 128 * KP) * 2;  // 139264 B
    const int SM64  = (2 * 128 * KP + 2 * 64 * KP) * 2;   // 104448 B
    cudaFuncSetAttribute(k_mma<128>, cudaFuncAttributeMaxDynamicSharedMemorySize, SM128);
    cudaFuncSetAttribute(k_mma<64>,  cudaFuncAttributeMaxDynamicSharedMemorySize, SM64);

    // edge_index dtype detection (int32 vs int64)
    k_detect<<<1, 1>>>((const unsigned int*)ei);

    // CSR build (counting sort by dst) + degrees
    k_zero_cnt<<<(NN + 255) / 256, 256>>>();
    k_hist<<<(EE + 255) / 256, 256>>>(ei);
    k_scan1<<<NBLK, 512>>>();
    k_scan2<<<1, 256>>>();
    k_scan3<<<(NN + 255) / 256, 256>>>();
    k_fill<<<(EE + 255) / 256, 256>>>(ei);

    // weight split + relayout
    k_prepW<<<64, 256>>>(W0, 128, WH0, WL0);
    k_prepW<<<64, 256>>>(W1, 128, WH1, WL1);
    k_prepW<<<32, 256>>>(W2, 64,  WH2, WL2);

    // h = relu(x @ W_in + b_in)
    k_inproj<<<(NN * 32 + 255) / 256, 256>>>(x, W_in, b_in, bufA);

    const int GB = (NN + 127) / 128;  // 782
    // layer 0
    k_mma<128><<<GB, 256, SM128>>>(bufA, WH0, WL0, bufB, bufH);
    k_agg128<<<(NN * 32 + 255) / 256, 256>>>(bufB, bufH, bufA, b0, g0, e0, m0, v0, bufC);
    // layer 1
    k_mma<128><<<GB, 256, SM128>>>(bufC, WH1, WL1, bufB, bufH);
    k_agg128<<<(NN * 32 + 255) / 256, 256>>>(bufB, bufH, bufC, b1, g1, e1, m1, v1, bufA);
    // layer 2 (final)
    k_mma<64><<<GB, 256, SM64>>>(bufA, WH2, WL2, bufB, bufH);
    k_agg64<<<(NN * 32 + 255) / 256, 256>>>(bufB, bufH, b2, g2, e2, m2, v2, out);
}

// round 8
// speedup vs baseline: 1.3203x; 1.1727x over previous
#include <cuda_runtime.h>
#include <cuda_bf16.h>
#include <cuda_fp16.h>
#include <cstdint>

#define NN 100000
#define EE 3200000
#define NBLK 196   // ceil(NN/512)
#define KK 128
#define KP 136     // padded smem row stride (elems): 272B = 68 words -> conflict-free frags

// ---------------- scratch (device globals; no allocations) ----------------
__device__ float g_bufA[NN * 128];
__device__ float g_bufC[NN * 128];
__device__ __half g_bufH[NN * 128];   // fp16 GEMM output (gather + self operand)
__device__ float g_dinv[NN];
__device__ int   g_cnt[NN];
__device__ int   g_rowptr[NN + 1];
__device__ int2  g_ecol[EE];          // {src col, dinv[src] bits}
__device__ int   g_bsum[256];
__device__ int   g_is64;
// split weights, [N][K] layout with stride KP
__device__ unsigned short g_Wsplit[6][128 * KP];

// ---------------- warp mma helper (baseline PTX, valid on sm_103) ----------------
__device__ __forceinline__ void mma16816(float* c, const uint32_t* a, uint32_t b0, uint32_t b1) {
    asm volatile(
        "mma.sync.aligned.m16n8k16.row.col.f32.bf16.bf16.f32 "
        "{%0,%1,%2,%3}, {%4,%5,%6,%7}, {%8,%9}, {%0,%1,%2,%3};"
        : "+f"(c[0]), "+f"(c[1]), "+f"(c[2]), "+f"(c[3])
        : "r"(a[0]), "r"(a[1]), "r"(a[2]), "r"(a[3]), "r"(b0), "r"(b1));
}

// ---------------- dtype detection for edge_index (parallel) ----------------
__global__ void k_detect(const unsigned int* __restrict__ ei_raw) {
    __shared__ unsigned int red[8];
    unsigned int o = 0;
    for (int i = threadIdx.x; i < 2048; i += 256) o |= ei_raw[2 * i + 1];
#pragma unroll
    for (int off = 16; off; off >>= 1) o |= __shfl_xor_sync(0xffffffffu, o, off);
    if ((threadIdx.x & 31) == 0) red[threadIdx.x >> 5] = o;
    __syncthreads();
    if (threadIdx.x == 0) {
        unsigned int t = 0;
#pragma unroll
        for (int i = 0; i < 8; i++) t |= red[i];
        g_is64 = (t == 0u) ? 1 : 0;
    }
}
__device__ __forceinline__ int load_edge(const void* ei, long long idx) {
    int v;
    if (g_is64) v = (int)((const long long*)ei)[idx];
    else        v = ((const int*)ei)[idx];
    return min(max(v, 0), NN - 1);
}

// ---------------- CSR build ----------------
__global__ void k_zero_cnt() {
    int i = blockIdx.x * blockDim.x + threadIdx.x;
    if (i < NN) g_cnt[i] = 0;
}
__global__ void k_hist(const void* __restrict__ ei) {
    int e = blockIdx.x * blockDim.x + threadIdx.x;
    if (e < EE) atomicAdd(&g_cnt[load_edge(ei, (long long)EE + e)], 1);
}
__global__ void k_scan1() {
    __shared__ int s[512];
    int t = threadIdx.x;
    int i = blockIdx.x * 512 + t;
    int v = (i < NN) ? g_cnt[i] : 0;
    s[t] = v;
    __syncthreads();
    for (int off = 1; off < 512; off <<= 1) {
        int x = (t >= off) ? s[t - off] : 0;
        __syncthreads();
        s[t] += x;
        __syncthreads();
    }
    if (i < NN) g_rowptr[i] = s[t] - v;
    if (t == 511) g_bsum[blockIdx.x] = s[511];
}
__global__ void k_scan2() {
    __shared__ int s[256];
    int t = threadIdx.x;
    int v = (t < NBLK) ? g_bsum[t] : 0;
    s[t] = v;
    __syncthreads();
    for (int off = 1; off < 256; off <<= 1) {
        int x = (t >= off) ? s[t - off] : 0;
        __syncthreads();
        s[t] += x;
        __syncthreads();
    }
    if (t < NBLK) g_bsum[t] = s[t] - v;
}
__global__ void k_scan3() {
    int i = blockIdx.x * blockDim.x + threadIdx.x;
    if (i < NN) {
        g_rowptr[i] += g_bsum[i >> 9];
        g_dinv[i] = rsqrtf((float)g_cnt[i] + 1.0f);
        g_cnt[i] = 0;
    }
    if (i == 0) g_rowptr[NN] = EE;
}
__global__ void k_fill(const void* __restrict__ ei) {
    int e = blockIdx.x * blockDim.x + threadIdx.x;
    if (e < EE) {
        int d = load_edge(ei, (long long)EE + e);
        int s = load_edge(ei, e);
        int p = atomicAdd(&g_cnt[d], 1);
        g_ecol[g_rowptr[d] + p] = make_int2(s, __float_as_int(g_dinv[s]));
    }
}

// ---------------- weight prep: W[K][N] fp32 -> hi/lo bf16 in [N][K] (stride KP) ----------------
__global__ void k_prepW(const float* __restrict__ W, int ncol,
                        unsigned short* __restrict__ bh, unsigned short* __restrict__ bl)
{
    int e = blockIdx.x * blockDim.x + threadIdx.x;
    if (e >= ncol * KK) return;
    int k = e / ncol, n = e % ncol;
    float w = W[e];
    __nv_bfloat16 h = __float2bfloat16(w);
    __nv_bfloat16 l = __float2bfloat16(w - __bfloat162float(h));
    bh[n * KP + k] = *(unsigned short*)&h;
    bl[n * KP + k] = *(unsigned short*)&l;
}

// ---------------- input projection: h = relu(x @ W_in + b_in) ----------------
__global__ __launch_bounds__(256) void k_inproj(
    const float* __restrict__ x, const float* __restrict__ Wi,
    const float* __restrict__ bi, float* __restrict__ h)
{
    __shared__ __align__(16) float Ws[7 * 128];
    for (int t = threadIdx.x; t < 7 * 128; t += 256) Ws[t] = Wi[t];
    __syncthreads();

    int gid = blockIdx.x * 256 + threadIdx.x;
    int i = gid >> 5, c = gid & 31;
    if (i >= NN) return;

    float xr[7];
#pragma unroll
    for (int k = 0; k < 7; k++) xr[k] = x[i * 7 + k];

    const float4* Ws4 = (const float4*)Ws;
    float4 acc = ((const float4*)bi)[c];
#pragma unroll
    for (int k = 0; k < 7; k++) {
        float4 w = Ws4[k * 32 + c];
        acc.x = fmaf(xr[k], w.x, acc.x);
        acc.y = fmaf(xr[k], w.y, acc.y);
        acc.z = fmaf(xr[k], w.z, acc.z);
        acc.w = fmaf(xr[k], w.w, acc.w);
    }
    acc.x = fmaxf(acc.x, 0.f); acc.y = fmaxf(acc.y, 0.f);
    acc.z = fmaxf(acc.z, 0.f); acc.w = fmaxf(acc.w, 0.f);
    ((float4*)h)[i * 32 + c] = acc;
}

// ---------------- tensor-core GEMM via mma.sync: H(fp16) = A[N,128] @ W[128,NCOL] ----------------
template <int NCOL>
__global__ __launch_bounds__(256) void k_mma(
    const float* __restrict__ A,
    const unsigned short* __restrict__ BH, const unsigned short* __restrict__ BL,
    __half* __restrict__ Hout)
{
    extern __shared__ unsigned short sm[];
    constexpr int A_HI = 0;
    constexpr int A_LO = 128 * KP;
    constexpr int B_HI = 2 * 128 * KP;
    constexpr int B_LO = 2 * 128 * KP + NCOL * KP;
    constexpr int WN = NCOL / 2;
    constexpr int NT = WN / 8;

    int tid = threadIdx.x;
    int wid = tid >> 5, lane = tid & 31;
    int g = lane >> 2, t = lane & 3;
    int wm = wid & 3, wn = wid >> 2;
    int m0 = blockIdx.x * 128;

    // ---- stage A: fp32 -> hi/lo bf16, padded smem ----
#pragma unroll 4
    for (int j = 0; j < 16; j++) {
        int i = tid + j * 256;
        int m = i >> 5, k4 = i & 31, k = k4 << 2;
        int row = min(m0 + m, NN - 1);
        float4 a = ((const float4*)A)[(size_t)row * 32 + k4];
        __nv_bfloat16 h0 = __float2bfloat16(a.x), h1 = __float2bfloat16(a.y);
        __nv_bfloat16 h2 = __float2bfloat16(a.z), h3 = __float2bfloat16(a.w);
        __nv_bfloat16 l0 = __float2bfloat16(a.x - __bfloat162float(h0));
        __nv_bfloat16 l1 = __float2bfloat16(a.y - __bfloat162float(h1));
        __nv_bfloat16 l2 = __float2bfloat16(a.z - __bfloat162float(h2));
        __nv_bfloat16 l3 = __float2bfloat16(a.w - __bfloat162float(h3));
        uint32_t h01 = ((uint32_t)*(unsigned short*)&h1 << 16) | *(unsigned short*)&h0;
        uint32_t h23 = ((uint32_t)*(unsigned short*)&h3 << 16) | *(unsigned short*)&h2;
        uint32_t l01 = ((uint32_t)*(unsigned short*)&l1 << 16) | *(unsigned short*)&l0;
        uint32_t l23 = ((uint32_t)*(unsigned short*)&l3 << 16) | *(unsigned short*)&l2;
        *(uint2*)&sm[A_HI + m * KP + k] = make_uint2(h01, h23);
        *(uint2*)&sm[A_LO + m * KP + k] = make_uint2(l01, l23);
    }
    // ---- stage B: raw copy ----
    {
        constexpr int CNT = NCOL * KP / 8;
        const uint4* gh = (const uint4*)BH;
        const uint4* gl = (const uint4*)BL;
        uint4* shh = (uint4*)&sm[B_HI];
        uint4* sll = (uint4*)&sm[B_LO];
        for (int i = tid; i < CNT; i += 256) { shh[i] = gh[i]; sll[i] = gl[i]; }
    }
    __syncthreads();

    float acc[2][NT][4];
#pragma unroll
    for (int mt = 0; mt < 2; mt++)
#pragma unroll
        for (int nt = 0; nt < NT; nt++)
#pragma unroll
            for (int q = 0; q < 4; q++) acc[mt][nt][q] = 0.f;

#pragma unroll
    for (int pass = 0; pass < 3; pass++) {
        const unsigned short* aS = sm + ((pass == 1) ? A_LO : A_HI);
        const unsigned short* bS = sm + ((pass == 2) ? B_LO : B_HI);
        int am = wm * 32;
#pragma unroll
        for (int k0 = 0; k0 < 128; k0 += 16) {
            uint32_t af[2][4];
#pragma unroll
            for (int mt = 0; mt < 2; mt++) {
                int r = am + mt * 16 + g;
                af[mt][0] = *(const uint32_t*)(aS + r * KP + k0 + t * 2);
                af[mt][1] = *(const uint32_t*)(aS + (r + 8) * KP + k0 + t * 2);
                af[mt][2] = *(const uint32_t*)(aS + r * KP + k0 + 8 + t * 2);
                af[mt][3] = *(const uint32_t*)(aS + (r + 8) * KP + k0 + 8 + t * 2);
            }
#pragma unroll
            for (int nt = 0; nt < NT; nt++) {
                int n = wn * WN + nt * 8 + g;
                uint32_t b0 = *(const uint32_t*)(bS + n * KP + k0 + t * 2);
                uint32_t b1 = *(const uint32_t*)(bS + n * KP + k0 + 8 + t * 2);
                mma16816(acc[0][nt], af[0], b0, b1);
                mma16816(acc[1][nt], af[1], b0, b1);
            }
        }
    }

    // ---- epilogue: fp16 stores only ----
#pragma unroll
    for (int mt = 0; mt < 2; mt++) {
        int r0 = m0 + wm * 32 + mt * 16 + g;
        int r1 = r0 + 8;
#pragma unroll
        for (int nt = 0; nt < NT; nt++) {
            int c = wn * WN + nt * 8 + t * 2;
            if (r0 < NN)
                *(__half2*)&Hout[(size_t)r0 * NCOL + c] =
                    __floats2half2_rn(acc[mt][nt][0], acc[mt][nt][1]);
            if (r1 < NN)
                *(__half2*)&Hout[(size_t)r1 * NCOL + c] =
                    __floats2half2_rn(acc[mt][nt][2], acc[mt][nt][3]);
        }
    }
}

// ---------------- fused agg (fp16 gather) + bias + BN + relu + residual (width 128) ----------------
__global__ __launch_bounds__(256) void k_agg128(
    const __half* __restrict__ linH, const float* __restrict__ resid,
    const float* __restrict__ bias, const float* __restrict__ gam,
    const float* __restrict__ bet, const float* __restrict__ mea,
    const float* __restrict__ var, float* __restrict__ out)
{
    __shared__ int2 s_e[8][32];
    int ws = threadIdx.x >> 5;
    int w = (blockIdx.x * blockDim.x + threadIdx.x) >> 5;
    int lane = threadIdx.x & 31;
    if (w >= NN) return;

    int start = g_rowptr[w], end = g_rowptr[w + 1];
    float di = g_dinv[w];
    const uint2* linH2 = (const uint2*)linH;   // 4 halves per lane

    float4 acc = make_float4(0.f, 0.f, 0.f, 0.f);
    for (int e0 = start; e0 < end; e0 += 32) {
        int idx = e0 + lane;
        if (idx < end) {
            int2 p = g_ecol[idx];
            s_e[ws][lane] = make_int2(p.x, __float_as_int(__int_as_float(p.y) * di));
        }
        __syncwarp();
        int nn = min(32, end - e0);
        int j = 0;
#pragma unroll 1
        for (; j + 4 <= nn; j += 4) {
            int2 p0 = s_e[ws][j + 0];
            int2 p1 = s_e[ws][j + 1];
            int2 p2 = s_e[ws][j + 2];
            int2 p3 = s_e[ws][j + 3];
            uint2 u0 = linH2[p0.x * 32 + lane];
            uint2 u1 = linH2[p1.x * 32 + lane];
            uint2 u2 = linH2[p2.x * 32 + lane];
            uint2 u3 = linH2[p3.x * 32 + lane];
            float c0 = __int_as_float(p0.y), c1 = __int_as_float(p1.y);
            float c2 = __int_as_float(p2.y), c3 = __int_as_float(p3.y);
            float2 a0 = __half22float2(*(__half2*)&u0.x), b0 = __half22float2(*(__half2*)&u0.y);
            float2 a1 = __half22float2(*(__half2*)&u1.x), b1 = __half22float2(*(__half2*)&u1.y);
            float2 a2 = __half22float2(*(__half2*)&u2.x), b2 = __half22float2(*(__half2*)&u2.y);
            float2 a3 = __half22float2(*(__half2*)&u3.x), b3 = __half22float2(*(__half2*)&u3.y);
            acc.x = fmaf(a0.x, c0, acc.x); acc.y = fmaf(a0.y, c0, acc.y);
            acc.z = fmaf(b0.x, c0, acc.z); acc.w = fmaf(b0.y, c0, acc.w);
            acc.x = fmaf(a1.x, c1, acc.x); acc.y = fmaf(a1.y, c1, acc.y);
            acc.z = fmaf(b1.x, c1, acc.z); acc.w = fmaf(b1.y, c1, acc.w);
            acc.x = fmaf(a2.x, c2, acc.x); acc.y = fmaf(a2.y, c2, acc.y);
            acc.z = fmaf(b2.x, c2, acc.z); acc.w = fmaf(b2.y, c2, acc.w);
            acc.x = fmaf(a3.x, c3, acc.x); acc.y = fmaf(a3.y, c3, acc.y);
            acc.z = fmaf(b3.x, c3, acc.z); acc.w = fmaf(b3.y, c3, acc.w);
        }
        for (; j < nn; j++) {
            int2 p = s_e[ws][j];
            uint2 u = linH2[p.x * 32 + lane];
            float c = __int_as_float(p.y);
            float2 a = __half22float2(*(__half2*)&u.x);
            float2 b = __half22float2(*(__half2*)&u.y);
            acc.x = fmaf(a.x, c, acc.x); acc.y = fmaf(a.y, c, acc.y);
            acc.z = fmaf(b.x, c, acc.z); acc.w = fmaf(b.y, c, acc.w);
        }
        __syncwarp();
    }
    // self term from fp16 shadow
    uint2 su = linH2[w * 32 + lane];
    float2 s0 = __half22float2(*(__half2*)&su.x);
    float2 s1 = __half22float2(*(__half2*)&su.y);
    float d2 = di * di;
    float4 bb = ((const float4*)bias)[lane];
    float4 gg = ((const float4*)gam)[lane];
    float4 ee = ((const float4*)bet)[lane];
    float4 mm = ((const float4*)mea)[lane];
    float4 vv = ((const float4*)var)[lane];
    float sx = gg.x * rsqrtf(vv.x + 1e-5f);
    float sy = gg.y * rsqrtf(vv.y + 1e-5f);
    float sz = gg.z * rsqrtf(vv.z + 1e-5f);
    float sw = gg.w * rsqrtf(vv.w + 1e-5f);

    float4 rr = ((const float4*)resid)[w * 32 + lane];
    float4 o;
    o.x = fmaxf((acc.x + s0.x * d2 + bb.x - mm.x) * sx + ee.x, 0.f) + rr.x;
    o.y = fmaxf((acc.y + s0.y * d2 + bb.y - mm.y) * sy + ee.y, 0.f) + rr.y;
    o.z = fmaxf((acc.z + s1.x * d2 + bb.z - mm.z) * sz + ee.z, 0.f) + rr.z;
    o.w = fmaxf((acc.w + s1.y * d2 + bb.w - mm.w) * sw + ee.w, 0.f) + rr.w;
    ((float4*)out)[w * 32 + lane] = o;
}

// ---------------- final layer agg (width 64, fp16 gather): conv + bias + BN only ----------------
__global__ __launch_bounds__(256) void k_agg64(
    const __half* __restrict__ linH,
    const float* __restrict__ bias, const float* __restrict__ gam,
    const float* __restrict__ bet, const float* __restrict__ mea,
    const float* __restrict__ var, float* __restrict__ out)
{
    __shared__ int2 s_e[8][32];
    int ws = threadIdx.x >> 5;
    int w = (blockIdx.x * blockDim.x + threadIdx.x) >> 5;
    int lane = threadIdx.x & 31;
    if (w >= NN) return;

    int start = g_rowptr[w], end = g_rowptr[w + 1];
    float di = g_dinv[w];
    const __half2* linH2 = (const __half2*)linH;   // 2 halves per lane

    float2 acc = make_float2(0.f, 0.f);
    for (int e0 = start; e0 < end; e0 += 32) {
        int idx = e0 + lane;
        if (idx < end) {
            int2 p = g_ecol[idx];
            s_e[ws][lane] = make_int2(p.x, __float_as_int(__int_as_float(p.y) * di));
        }
        __syncwarp();
        int nn = min(32, end - e0);
        int j = 0;
#pragma unroll 1
        for (; j + 4 <= nn; j += 4) {
            int2 p0 = s_e[ws][j + 0];
            int2 p1 = s_e[ws][j + 1];
            int2 p2 = s_e[ws][j + 2];
            int2 p3 = s_e[ws][j + 3];
            __half2 u0 = linH2[p0.x * 32 + lane];
            __half2 u1 = linH2[p1.x * 32 + lane];
            __half2 u2 = linH2[p2.x * 32 + lane];
            __half2 u3 = linH2[p3.x * 32 + lane];
            float2 f0 = __half22float2(u0), f1 = __half22float2(u1);
            float2 f2 = __half22float2(u2), f3 = __half22float2(u3);
            float c0 = __int_as_float(p0.y), c1 = __int_as_float(p1.y);
            float c2 = __int_as_float(p2.y), c3 = __int_as_float(p3.y);
            acc.x = fmaf(f0.x, c0, acc.x); acc.y = fmaf(f0.y, c0, acc.y);
            acc.x = fmaf(f1.x, c1, acc.x); acc.y = fmaf(f1.y, c1, acc.y);
            acc.x = fmaf(f2.x, c2, acc.x); acc.y = fmaf(f2.y, c2, acc.y);
            acc.x = fmaf(f3.x, c3, acc.x); acc.y = fmaf(f3.y, c3, acc.y);
        }
        for (; j < nn; j++) {
            int2 p = s_e[ws][j];
            float2 f = __half22float2(linH2[p.x * 32 + lane]);
            float c = __int_as_float(p.y);
            acc.x = fmaf(f.x, c, acc.x); acc.y = fmaf(f.y, c, acc.y);
        }
        __syncwarp();
    }
    float2 sv = __half22float2(linH2[w * 32 + lane]);
    float d2 = di * di;
    float2 bb = ((const float2*)bias)[lane];
    float2 gg = ((const float2*)gam)[lane];
    float2 ee = ((const float2*)bet)[lane];
    float2 mm = ((const float2*)mea)[lane];
    float2 vv = ((const float2*)var)[lane];
    float sx = gg.x * rsqrtf(vv.x + 1e-5f);
    float sy = gg.y * rsqrtf(vv.y + 1e-5f);

    float2 o;
    o.x = (acc.x + sv.x * d2 + bb.x - mm.x) * sx + ee.x;
    o.y = (acc.y + sv.y * d2 + bb.y - mm.y) * sy + ee.y;
    ((float2*)out)[w * 32 + lane] = o;
}

// ---------------- launch ----------------
extern "C" void kernel_launch(void* const* d_in, const int* in_sizes, int n_in,
                              void* d_out, int out_size)
{
    const float* x    = (const float*)d_in[0];
    const void*  ei   = d_in[1];
    const float* W_in = (const float*)d_in[2];
    const float* b_in = (const float*)d_in[3];
    const float* W0 = (const float*)d_in[4];
    const float* b0 = (const float*)d_in[5];
    const float* g0 = (const float*)d_in[6];
    const float* e0 = (const float*)d_in[7];
    const float* m0 = (const float*)d_in[8];
    const float* v0 = (const float*)d_in[9];
    const float* W1 = (const float*)d_in[10];
    const float* b1 = (const float*)d_in[11];
    const float* g1 = (const float*)d_in[12];
    const float* e1 = (const float*)d_in[13];
    const float* m1 = (const float*)d_in[14];
    const float* v1 = (const float*)d_in[15];
    const float* W2 = (const float*)d_in[16];
    const float* b2 = (const float*)d_in[17];
    const float* g2 = (const float*)d_in[18];
    const float* e2 = (const float*)d_in[19];
    const float* m2 = (const float*)d_in[20];
    const float* v2 = (const float*)d_in[21];
    float* out = (float*)d_out;

    float *bufA, *bufC;
    __half* bufH;
    unsigned short* wsp;
    cudaGetSymbolAddress((void**)&bufA, g_bufA);
    cudaGetSymbolAddress((void**)&bufC, g_bufC);
    cudaGetSymbolAddress((void**)&bufH, g_bufH);
    cudaGetSymbolAddress((void**)&wsp,  g_Wsplit);
    unsigned short* WH0 = wsp + 0 * 128 * KP;
    unsigned short* WL0 = wsp + 1 * 128 * KP;
    unsigned short* WH1 = wsp + 2 * 128 * KP;
    unsigned short* WL1 = wsp + 3 * 128 * KP;
    unsigned short* WH2 = wsp + 4 * 128 * KP;
    unsigned short* WL2 = wsp + 5 * 128 * KP;

    const int SM128 = (2 * 128 * KP + 2 * 128 * KP) * 2;  // 139264 B
    const int SM64  = (2 * 128 * KP + 2 * 64 * KP) * 2;   // 104448 B
    cudaFuncSetAttribute(k_mma<128>, cudaFuncAttributeMaxDynamicSharedMemorySize, SM128);
    cudaFuncSetAttribute(k_mma<64>,  cudaFuncAttributeMaxDynamicSharedMemorySize, SM64);

    // edge_index dtype detection (int32 vs int64)
    k_detect<<<1, 256>>>((const unsigned int*)ei);

    // CSR build (counting sort by dst) + degrees
    k_zero_cnt<<<(NN + 255) / 256, 256>>>();
    k_hist<<<(EE + 255) / 256, 256>>>(ei);
    k_scan1<<<NBLK, 512>>>();
    k_scan2<<<1, 256>>>();
    k_scan3<<<(NN + 255) / 256, 256>>>();
    k_fill<<<(EE + 255) / 256, 256>>>(ei);

    // weight split + relayout
    k_prepW<<<64, 256>>>(W0, 128, WH0, WL0);
    k_prepW<<<64, 256>>>(W1, 128, WH1, WL1);
    k_prepW<<<32, 256>>>(W2, 64,  WH2, WL2);

    // h = relu(x @ W_in + b_in)
    k_inproj<<<(NN * 32 + 255) / 256, 256>>>(x, W_in, b_in, bufA);

    const int GB = (NN + 127) / 128;  // 782
    // layer 0
    k_mma<128><<<GB, 256, SM128>>>(bufA, WH0, WL0, bufH);
    k_agg128<<<(NN * 32 + 255) / 256, 256>>>(bufH, bufA, b0, g0, e0, m0, v0, bufC);
    // layer 1
    k_mma<128><<<GB, 256, SM128>>>(bufC, WH1, WL1, bufH);
    k_agg128<<<(NN * 32 + 255) / 256, 256>>>(bufH, bufC, b1, g1, e1, m1, v1, bufA);
    // layer 2 (final)
    k_mma<64><<<GB, 256, SM64>>>(bufA, WH2, WL2, bufH);
    k_agg64<<<(NN * 32 + 255) / 256, 256>>>(bufH, b2, g2, e2, m2, v2, out);
}

// round 9
// speedup vs baseline: 1.3952x; 1.0567x over previous
#include <cuda_runtime.h>
#include <cuda_bf16.h>
#include <cuda_fp16.h>
#include <cstdint>

#define NN 100000
#define EE 3200000
#define NBLK 196   // ceil(NN/512)
#define KK 128
#define KP 136     // padded smem row stride (elems): 272B = 68 words -> conflict-free frags

// ---------------- scratch (device globals; no allocations) ----------------
__device__ float g_bufA[NN * 128];
__device__ float g_bufC[NN * 128];
__device__ __half g_bufH[NN * 128];   // fp16 premultiplied GEMM output: hs = dinv*h
__device__ float g_dinv[NN];
__device__ int   g_cnt[NN];
__device__ int   g_rowptr[NN + 1];
__device__ int   g_ecol[EE];          // src col only (coef folded into hs)
__device__ int   g_bsum[256];
__device__ int   g_is64;
// split weights, [N][K] layout with stride KP
__device__ unsigned short g_Wsplit[6][128 * KP];

// ---------------- warp mma helper (baseline PTX, valid on sm_103) ----------------
__device__ __forceinline__ void mma16816(float* c, const uint32_t* a, uint32_t b0, uint32_t b1) {
    asm volatile(
        "mma.sync.aligned.m16n8k16.row.col.f32.bf16.bf16.f32 "
        "{%0,%1,%2,%3}, {%4,%5,%6,%7}, {%8,%9}, {%0,%1,%2,%3};"
        : "+f"(c[0]), "+f"(c[1]), "+f"(c[2]), "+f"(c[3])
        : "r"(a[0]), "r"(a[1]), "r"(a[2]), "r"(a[3]), "r"(b0), "r"(b1));
}

// ---------------- zero counters + edge dtype detection (merged) ----------------
__global__ void k_zerodetect(const unsigned int* __restrict__ ei_raw) {
    int i = blockIdx.x * blockDim.x + threadIdx.x;
    if (i < NN) g_cnt[i] = 0;
    if (blockIdx.x == 0) {
        __shared__ unsigned int red[8];
        unsigned int o = 0;
        for (int j = threadIdx.x; j < 2048; j += 256) o |= ei_raw[2 * j + 1];
#pragma unroll
        for (int off = 16; off; off >>= 1) o |= __shfl_xor_sync(0xffffffffu, o, off);
        if ((threadIdx.x & 31) == 0) red[threadIdx.x >> 5] = o;
        __syncthreads();
        if (threadIdx.x == 0) {
            unsigned int t = 0;
#pragma unroll
            for (int j = 0; j < 8; j++) t |= red[j];
            g_is64 = (t == 0u) ? 1 : 0;
        }
    }
}
__device__ __forceinline__ int load_edge(const void* ei, long long idx) {
    int v;
    if (g_is64) v = (int)((const long long*)ei)[idx];
    else        v = ((const int*)ei)[idx];
    return min(max(v, 0), NN - 1);
}

// ---------------- CSR build ----------------
__global__ void k_hist(const void* __restrict__ ei) {
    int e = blockIdx.x * blockDim.x + threadIdx.x;
    if (e < EE) atomicAdd(&g_cnt[load_edge(ei, (long long)EE + e)], 1);
}
__global__ void k_scan1() {
    __shared__ int s[512];
    int t = threadIdx.x;
    int i = blockIdx.x * 512 + t;
    int v = (i < NN) ? g_cnt[i] : 0;
    s[t] = v;
    __syncthreads();
    for (int off = 1; off < 512; off <<= 1) {
        int x = (t >= off) ? s[t - off] : 0;
        __syncthreads();
        s[t] += x;
        __syncthreads();
    }
    if (i < NN) g_rowptr[i] = s[t] - v;
    if (t == 511) g_bsum[blockIdx.x] = s[511];
}
// scan of block partials folded in: every block redoes the 196-entry scan in smem
__global__ void k_scan3() {
    __shared__ int sb[256];
    int t = threadIdx.x;
    int v = (t < NBLK) ? g_bsum[t] : 0;
    sb[t] = v;
    __syncthreads();
    for (int off = 1; off < 256; off <<= 1) {
        int x = (t >= off) ? sb[t - off] : 0;
        __syncthreads();
        sb[t] += x;
        __syncthreads();
    }
    int excl = sb[t] - v;
    __syncthreads();
    sb[t] = excl;
    __syncthreads();

    int i = blockIdx.x * blockDim.x + t;
    if (i < NN) {
        g_rowptr[i] += sb[i >> 9];
        g_dinv[i] = rsqrtf((float)g_cnt[i] + 1.0f);
        g_cnt[i] = 0;
    }
    if (i == 0) g_rowptr[NN] = EE;
}
__global__ void k_fill(const void* __restrict__ ei) {
    int e = blockIdx.x * blockDim.x + threadIdx.x;
    if (e < EE) {
        int d = load_edge(ei, (long long)EE + e);
        int s = load_edge(ei, e);
        int p = atomicAdd(&g_cnt[d], 1);
        g_ecol[g_rowptr[d] + p] = s;
    }
}

// ---------------- weight prep: W[K][N] fp32 -> hi/lo bf16 in [N][K] (stride KP) ----------------
__global__ void k_prepW(const float* __restrict__ W, int ncol,
                        unsigned short* __restrict__ bh, unsigned short* __restrict__ bl)
{
    int e = blockIdx.x * blockDim.x + threadIdx.x;
    if (e >= ncol * KK) return;
    int k = e / ncol, n = e % ncol;
    float w = W[e];
    __nv_bfloat16 h = __float2bfloat16(w);
    __nv_bfloat16 l = __float2bfloat16(w - __bfloat162float(h));
    bh[n * KP + k] = *(unsigned short*)&h;
    bl[n * KP + k] = *(unsigned short*)&l;
}

// ---------------- input projection: h = relu(x @ W_in + b_in) ----------------
__global__ __launch_bounds__(256) void k_inproj(
    const float* __restrict__ x, const float* __restrict__ Wi,
    const float* __restrict__ bi, float* __restrict__ h)
{
    __shared__ __align__(16) float Ws[7 * 128];
    for (int t = threadIdx.x; t < 7 * 128; t += 256) Ws[t] = Wi[t];
    __syncthreads();

    int gid = blockIdx.x * 256 + threadIdx.x;
    int i = gid >> 5, c = gid & 31;
    if (i >= NN) return;

    float xr[7];
#pragma unroll
    for (int k = 0; k < 7; k++) xr[k] = x[i * 7 + k];

    const float4* Ws4 = (const float4*)Ws;
    float4 acc = ((const float4*)bi)[c];
#pragma unroll
    for (int k = 0; k < 7; k++) {
        float4 w = Ws4[k * 32 + c];
        acc.x = fmaf(xr[k], w.x, acc.x);
        acc.y = fmaf(xr[k], w.y, acc.y);
        acc.z = fmaf(xr[k], w.z, acc.z);
        acc.w = fmaf(xr[k], w.w, acc.w);
    }
    acc.x = fmaxf(acc.x, 0.f); acc.y = fmaxf(acc.y, 0.f);
    acc.z = fmaxf(acc.z, 0.f); acc.w = fmaxf(acc.w, 0.f);
    ((float4*)h)[i * 32 + c] = acc;
}

// ---------------- tensor-core GEMM via mma.sync: Hout(fp16) = dinv .* (A[N,128] @ W) ----------------
template <int NCOL>
__global__ __launch_bounds__(256) void k_mma(
    const float* __restrict__ A,
    const unsigned short* __restrict__ BH, const unsigned short* __restrict__ BL,
    __half* __restrict__ Hout)
{
    extern __shared__ unsigned short sm[];
    constexpr int A_HI = 0;
    constexpr int A_LO = 128 * KP;
    constexpr int B_HI = 2 * 128 * KP;
    constexpr int B_LO = 2 * 128 * KP + NCOL * KP;
    constexpr int WN = NCOL / 2;
    constexpr int NT = WN / 8;

    int tid = threadIdx.x;
    int wid = tid >> 5, lane = tid & 31;
    int g = lane >> 2, t = lane & 3;
    int wm = wid & 3, wn = wid >> 2;
    int m0 = blockIdx.x * 128;

    // ---- stage A: fp32 -> hi/lo bf16, padded smem ----
#pragma unroll 4
    for (int j = 0; j < 16; j++) {
        int i = tid + j * 256;
        int m = i >> 5, k4 = i & 31, k = k4 << 2;
        int row = min(m0 + m, NN - 1);
        float4 a = ((const float4*)A)[(size_t)row * 32 + k4];
        __nv_bfloat16 h0 = __float2bfloat16(a.x), h1 = __float2bfloat16(a.y);
        __nv_bfloat16 h2 = __float2bfloat16(a.z), h3 = __float2bfloat16(a.w);
        __nv_bfloat16 l0 = __float2bfloat16(a.x - __bfloat162float(h0));
        __nv_bfloat16 l1 = __float2bfloat16(a.y - __bfloat162float(h1));
        __nv_bfloat16 l2 = __float2bfloat16(a.z - __bfloat162float(h2));
        __nv_bfloat16 l3 = __float2bfloat16(a.w - __bfloat162float(h3));
        uint32_t h01 = ((uint32_t)*(unsigned short*)&h1 << 16) | *(unsigned short*)&h0;
        uint32_t h23 = ((uint32_t)*(unsigned short*)&h3 << 16) | *(unsigned short*)&h2;
        uint32_t l01 = ((uint32_t)*(unsigned short*)&l1 << 16) | *(unsigned short*)&l0;
        uint32_t l23 = ((uint32_t)*(unsigned short*)&l3 << 16) | *(unsigned short*)&l2;
        *(uint2*)&sm[A_HI + m * KP + k] = make_uint2(h01, h23);
        *(uint2*)&sm[A_LO + m * KP + k] = make_uint2(l01, l23);
    }
    // ---- stage B: raw copy ----
    {
        constexpr int CNT = NCOL * KP / 8;
        const uint4* gh = (const uint4*)BH;
        const uint4* gl = (const uint4*)BL;
        uint4* shh = (uint4*)&sm[B_HI];
        uint4* sll = (uint4*)&sm[B_LO];
        for (int i = tid; i < CNT; i += 256) { shh[i] = gh[i]; sll[i] = gl[i]; }
    }
    __syncthreads();

    float acc[2][NT][4];
#pragma unroll
    for (int mt = 0; mt < 2; mt++)
#pragma unroll
        for (int nt = 0; nt < NT; nt++)
#pragma unroll
            for (int q = 0; q < 4; q++) acc[mt][nt][q] = 0.f;

#pragma unroll
    for (int pass = 0; pass < 3; pass++) {
        const unsigned short* aS = sm + ((pass == 1) ? A_LO : A_HI);
        const unsigned short* bS = sm + ((pass == 2) ? B_LO : B_HI);
        int am = wm * 32;
#pragma unroll
        for (int k0 = 0; k0 < 128; k0 += 16) {
            uint32_t af[2][4];
#pragma unroll
            for (int mt = 0; mt < 2; mt++) {
                int r = am + mt * 16 + g;
                af[mt][0] = *(const uint32_t*)(aS + r * KP + k0 + t * 2);
                af[mt][1] = *(const uint32_t*)(aS + (r + 8) * KP + k0 + t * 2);
                af[mt][2] = *(const uint32_t*)(aS + r * KP + k0 + 8 + t * 2);
                af[mt][3] = *(const uint32_t*)(aS + (r + 8) * KP + k0 + 8 + t * 2);
            }
#pragma unroll
            for (int nt = 0; nt < NT; nt++) {
                int n = wn * WN + nt * 8 + g;
                uint32_t b0 = *(const uint32_t*)(bS + n * KP + k0 + t * 2);
                uint32_t b1 = *(const uint32_t*)(bS + n * KP + k0 + 8 + t * 2);
                mma16816(acc[0][nt], af[0], b0, b1);
                mma16816(acc[1][nt], af[1], b0, b1);
            }
        }
    }

    // ---- epilogue: premultiply by dinv[row], fp16 stores ----
#pragma unroll
    for (int mt = 0; mt < 2; mt++) {
        int r0 = m0 + wm * 32 + mt * 16 + g;
        int r1 = r0 + 8;
        if (r0 < NN) {
            float dv = g_dinv[r0];
#pragma unroll
            for (int nt = 0; nt < NT; nt++) {
                int c = wn * WN + nt * 8 + t * 2;
                *(__half2*)&Hout[(size_t)r0 * NCOL + c] =
                    __floats2half2_rn(acc[mt][nt][0] * dv, acc[mt][nt][1] * dv);
            }
        }
        if (r1 < NN) {
            float dv = g_dinv[r1];
#pragma unroll
            for (int nt = 0; nt < NT; nt++) {
                int c = wn * WN + nt * 8 + t * 2;
                *(__half2*)&Hout[(size_t)r1 * NCOL + c] =
                    __floats2half2_rn(acc[mt][nt][2] * dv, acc[mt][nt][3] * dv);
            }
        }
    }
}

// ---------------- fused agg (premultiplied fp16 gather) + bias + BN + relu + residual (width 128) ----------------
__global__ __launch_bounds__(256) void k_agg128(
    const __half* __restrict__ linH, const float* __restrict__ resid,
    const float* __restrict__ bias, const float* __restrict__ gam,
    const float* __restrict__ bet, const float* __restrict__ mea,
    const float* __restrict__ var, float* __restrict__ out)
{
    __shared__ int s_c[8][32];
    int ws = threadIdx.x >> 5;
    int w = (blockIdx.x * blockDim.x + threadIdx.x) >> 5;
    int lane = threadIdx.x & 31;
    if (w >= NN) return;

    int start = g_rowptr[w], end = g_rowptr[w + 1];
    float di = g_dinv[w];
    const uint2* linH2 = (const uint2*)linH;   // 4 halves per lane

    float4 acc = make_float4(0.f, 0.f, 0.f, 0.f);
    for (int e0 = start; e0 < end; e0 += 32) {
        int idx = e0 + lane;
        if (idx < end) s_c[ws][lane] = g_ecol[idx];
        __syncwarp();
        int nn = min(32, end - e0);
        int j = 0;
#pragma unroll 1
        for (; j + 4 <= nn; j += 4) {
            int c0 = s_c[ws][j + 0];
            int c1 = s_c[ws][j + 1];
            int c2 = s_c[ws][j + 2];
            int c3 = s_c[ws][j + 3];
            uint2 u0 = linH2[c0 * 32 + lane];
            uint2 u1 = linH2[c1 * 32 + lane];
            uint2 u2 = linH2[c2 * 32 + lane];
            uint2 u3 = linH2[c3 * 32 + lane];
            float2 a0 = __half22float2(*(__half2*)&u0.x), b0 = __half22float2(*(__half2*)&u0.y);
            float2 a1 = __half22float2(*(__half2*)&u1.x), b1 = __half22float2(*(__half2*)&u1.y);
            float2 a2 = __half22float2(*(__half2*)&u2.x), b2 = __half22float2(*(__half2*)&u2.y);
            float2 a3 = __half22float2(*(__half2*)&u3.x), b3 = __half22float2(*(__half2*)&u3.y);
            acc.x += a0.x + a1.x; acc.y += a0.y + a1.y;
            acc.z += b0.x + b1.x; acc.w += b0.y + b1.y;
            acc.x += a2.x + a3.x; acc.y += a2.y + a3.y;
            acc.z += b2.x + b3.x; acc.w += b2.y + b3.y;
        }
        for (; j < nn; j++) {
            int c = s_c[ws][j];
            uint2 u = linH2[c * 32 + lane];
            float2 a = __half22float2(*(__half2*)&u.x);
            float2 b = __half22float2(*(__half2*)&u.y);
            acc.x += a.x; acc.y += a.y;
            acc.z += b.x; acc.w += b.y;
        }
        __syncwarp();
    }
    // self term: + hs[w] (then whole sum * di)
    uint2 su = linH2[w * 32 + lane];
    float2 s0 = __half22float2(*(__half2*)&su.x);
    float2 s1 = __half22float2(*(__half2*)&su.y);
    acc.x += s0.x; acc.y += s0.y; acc.z += s1.x; acc.w += s1.y;

    float4 bb = ((const float4*)bias)[lane];
    float4 gg = ((const float4*)gam)[lane];
    float4 ee = ((const float4*)bet)[lane];
    float4 mm = ((const float4*)mea)[lane];
    float4 vv = ((const float4*)var)[lane];
    float sx = gg.x * rsqrtf(vv.x + 1e-5f);
    float sy = gg.y * rsqrtf(vv.y + 1e-5f);
    float sz = gg.z * rsqrtf(vv.z + 1e-5f);
    float sw = gg.w * rsqrtf(vv.w + 1e-5f);

    float4 rr = ((const float4*)resid)[w * 32 + lane];
    float4 o;
    o.x = fmaxf((fmaf(acc.x, di, bb.x) - mm.x) * sx + ee.x, 0.f) + rr.x;
    o.y = fmaxf((fmaf(acc.y, di, bb.y) - mm.y) * sy + ee.y, 0.f) + rr.y;
    o.z = fmaxf((fmaf(acc.z, di, bb.z) - mm.z) * sz + ee.z, 0.f) + rr.z;
    o.w = fmaxf((fmaf(acc.w, di, bb.w) - mm.w) * sw + ee.w, 0.f) + rr.w;
    ((float4*)out)[w * 32 + lane] = o;
}

// ---------------- final layer agg (width 64): conv + bias + BN only ----------------
__global__ __launch_bounds__(256) void k_agg64(
    const __half* __restrict__ linH,
    const float* __restrict__ bias, const float* __restrict__ gam,
    const float* __restrict__ bet, const float* __restrict__ mea,
    const float* __restrict__ var, float* __restrict__ out)
{
    __shared__ int s_c[8][32];
    int ws = threadIdx.x >> 5;
    int w = (blockIdx.x * blockDim.x + threadIdx.x) >> 5;
    int lane = threadIdx.x & 31;
    if (w >= NN) return;

    int start = g_rowptr[w], end = g_rowptr[w + 1];
    float di = g_dinv[w];
    const __half2* linH2 = (const __half2*)linH;   // 2 halves per lane

    float2 acc = make_float2(0.f, 0.f);
    for (int e0 = start; e0 < end; e0 += 32) {
        int idx = e0 + lane;
        if (idx < end) s_c[ws][lane] = g_ecol[idx];
        __syncwarp();
        int nn = min(32, end - e0);
        int j = 0;
#pragma unroll 1
        for (; j + 4 <= nn; j += 4) {
            int c0 = s_c[ws][j + 0];
            int c1 = s_c[ws][j + 1];
            int c2 = s_c[ws][j + 2];
            int c3 = s_c[ws][j + 3];
            float2 f0 = __half22float2(linH2[c0 * 32 + lane]);
            float2 f1 = __half22float2(linH2[c1 * 32 + lane]);
            float2 f2 = __half22float2(linH2[c2 * 32 + lane]);
            float2 f3 = __half22float2(linH2[c3 * 32 + lane]);
            acc.x += f0.x + f1.x; acc.y += f0.y + f1.y;
            acc.x += f2.x + f3.x; acc.y += f2.y + f3.y;
        }
        for (; j < nn; j++) {
            int c = s_c[ws][j];
            float2 f = __half22float2(linH2[c * 32 + lane]);
            acc.x += f.x; acc.y += f.y;
        }
        __syncwarp();
    }
    float2 sv = __half22float2(linH2[w * 32 + lane]);
    acc.x += sv.x; acc.y += sv.y;

    float2 bb = ((const float2*)bias)[lane];
    float2 gg = ((const float2*)gam)[lane];
    float2 ee = ((const float2*)bet)[lane];
    float2 mm = ((const float2*)mea)[lane];
    float2 vv = ((const float2*)var)[lane];
    float sx = gg.x * rsqrtf(vv.x + 1e-5f);
    float sy = gg.y * rsqrtf(vv.y + 1e-5f);

    float2 o;
    o.x = (fmaf(acc.x, di, bb.x) - mm.x) * sx + ee.x;
    o.y = (fmaf(acc.y, di, bb.y) - mm.y) * sy + ee.y;
    ((float2*)out)[w * 32 + lane] = o;
}

// ---------------- launch ----------------
extern "C" void kernel_launch(void* const* d_in, const int* in_sizes, int n_in,
                              void* d_out, int out_size)
{
    const float* x    = (const float*)d_in[0];
    const void*  ei   = d_in[1];
    const float* W_in = (const float*)d_in[2];
    const float* b_in = (const float*)d_in[3];
    const float* W0 = (const float*)d_in[4];
    const float* b0 = (const float*)d_in[5];
    const float* g0 = (const float*)d_in[6];
    const float* e0 = (const float*)d_in[7];
    const float* m0 = (const float*)d_in[8];
    const float* v0 = (const float*)d_in[9];
    const float* W1 = (const float*)d_in[10];
    const float* b1 = (const float*)d_in[11];
    const float* g1 = (const float*)d_in[12];
    const float* e1 = (const float*)d_in[13];
    const float* m1 = (const float*)d_in[14];
    const float* v1 = (const float*)d_in[15];
    const float* W2 = (const float*)d_in[16];
    const float* b2 = (const float*)d_in[17];
    const float* g2 = (const float*)d_in[18];
    const float* e2 = (const float*)d_in[19];
    const float* m2 = (const float*)d_in[20];
    const float* v2 = (const float*)d_in[21];
    float* out = (float*)d_out;

    float *bufA, *bufC;
    __half* bufH;
    unsigned short* wsp;
    cudaGetSymbolAddress((void**)&bufA, g_bufA);
    cudaGetSymbolAddress((void**)&bufC, g_bufC);
    cudaGetSymbolAddress((void**)&bufH, g_bufH);
    cudaGetSymbolAddress((void**)&wsp,  g_Wsplit);
    unsigned short* WH0 = wsp + 0 * 128 * KP;
    unsigned short* WL0 = wsp + 1 * 128 * KP;
    unsigned short* WH1 = wsp + 2 * 128 * KP;
    unsigned short* WL1 = wsp + 3 * 128 * KP;
    unsigned short* WH2 = wsp + 4 * 128 * KP;
    unsigned short* WL2 = wsp + 5 * 128 * KP;

    const int SM128 = (2 * 128 * KP + 2 * 128 * KP) * 2;  // 139264 B
    const int SM64  = (2 * 128 * KP + 2 * 64 * KP) * 2;   // 104448 B
    cudaFuncSetAttribute(k_mma<128>, cudaFuncAttributeMaxDynamicSharedMemorySize, SM128);
    cudaFuncSetAttribute(k_mma<64>,  cudaFuncAttributeMaxDynamicSharedMemorySize, SM64);

    // CSR build (counting sort by dst) + degrees; detect merged into zero
    k_zerodetect<<<(NN + 255) / 256, 256>>>((const unsigned int*)ei);
    k_hist<<<(EE + 255) / 256, 256>>>(ei);
    k_scan1<<<NBLK, 512>>>();
    k_scan3<<<(NN + 255) / 256, 256>>>();
    k_fill<<<(EE + 255) / 256, 256>>>(ei);

    // weight split + relayout
    k_prepW<<<64, 256>>>(W0, 128, WH0, WL0);
    k_prepW<<<64, 256>>>(W1, 128, WH1, WL1);
    k_prepW<<<32, 256>>>(W2, 64,  WH2, WL2);

    // h = relu(x @ W_in + b_in)
    k_inproj<<<(NN * 32 + 255) / 256, 256>>>(x, W_in, b_in, bufA);

    const int GB = (NN + 127) / 128;  // 782
    // layer 0
    k_mma<128><<<GB, 256, SM128>>>(bufA, WH0, WL0, bufH);
    k_agg128<<<(NN * 32 + 255) / 256, 256>>>(bufH, bufA, b0, g0, e0, m0, v0, bufC);
    // layer 1
    k_mma<128><<<GB, 256, SM128>>>(bufC, WH1, WL1, bufH);
    k_agg128<<<(NN * 32 + 255) / 256, 256>>>(bufH, bufC, b1, g1, e1, m1, v1, bufA);
    // layer 2 (final)
    k_mma<64><<<GB, 256, SM64>>>(bufA, WH2, WL2, bufH);
    k_agg64<<<(NN * 32 + 255) / 256, 256>>>(bufH, b2, g2, e2, m2, v2, out);
}

// round 13
// speedup vs baseline: 1.4482x; 1.0380x over previous
#include <cuda_runtime.h>
#include <cuda_bf16.h>
#include <cuda_fp16.h>
#include <cstdint>

#define NN 100000
#define EE 3200000
#define NBLK 196   // ceil(NN/512)
#define KK 128
#define KP 136     // padded smem row stride (elems): 272B = 68 words -> conflict-free frags

// ---------------- scratch (device globals; no allocations) ----------------
__device__ float g_bufA[NN * 128];
__device__ float g_bufC[NN * 128];
__device__ __half g_bufH[NN * 128];   // fp16 premultiplied GEMM output: hs = dinv*h
__device__ float g_dinv[NN];
__device__ int   g_cnt[NN];           // degree counts, then reused as fill cursor (= rowptr)
__device__ int   g_rowptr[NN + 1];
__device__ int   g_ecol[EE];          // src col only (coef folded into hs)
__device__ int   g_bsum[256];
__device__ int   g_is64;
// split weights, [N][K] layout with stride KP
__device__ unsigned short g_Wsplit[6][128 * KP];

// ---------------- warp mma helper (baseline PTX, valid on sm_103) ----------------
__device__ __forceinline__ void mma16816(float* c, const uint32_t* a, uint32_t b0, uint32_t b1) {
    asm volatile(
        "mma.sync.aligned.m16n8k16.row.col.f32.bf16.bf16.f32 "
        "{%0,%1,%2,%3}, {%4,%5,%6,%7}, {%8,%9}, {%0,%1,%2,%3};"
        : "+f"(c[0]), "+f"(c[1]), "+f"(c[2]), "+f"(c[3])
        : "r"(a[0]), "r"(a[1]), "r"(a[2]), "r"(a[3]), "r"(b0), "r"(b1));
}

// ---------------- zero counters + edge dtype detection (merged) ----------------
__global__ void k_zerodetect(const unsigned int* __restrict__ ei_raw) {
    int i = blockIdx.x * blockDim.x + threadIdx.x;
    if (i < NN) g_cnt[i] = 0;
    if (blockIdx.x == 0) {
        __shared__ unsigned int red[8];
        unsigned int o = 0;
        for (int j = threadIdx.x; j < 2048; j += 256) o |= ei_raw[2 * j + 1];
#pragma unroll
        for (int off = 16; off; off >>= 1) o |= __shfl_xor_sync(0xffffffffu, o, off);
        if ((threadIdx.x & 31) == 0) red[threadIdx.x >> 5] = o;
        __syncthreads();
        if (threadIdx.x == 0) {
            unsigned int t = 0;
#pragma unroll
            for (int j = 0; j < 8; j++) t |= red[j];
            g_is64 = (t == 0u) ? 1 : 0;
        }
    }
}
__device__ __forceinline__ int load_edge(const void* ei, long long idx) {
    int v;
    if (g_is64) v = (int)((const long long*)ei)[idx];
    else        v = ((const int*)ei)[idx];
    return min(max(v, 0), NN - 1);
}

// ---------------- CSR build ----------------
__global__ void k_hist(const void* __restrict__ ei) {
    int e = blockIdx.x * blockDim.x + threadIdx.x;
    if (e < EE) atomicAdd(&g_cnt[load_edge(ei, (long long)EE + e)], 1);
}
__global__ void k_scan1() {
    __shared__ int s[512];
    int t = threadIdx.x;
    int i = blockIdx.x * 512 + t;
    int v = (i < NN) ? g_cnt[i] : 0;
    s[t] = v;
    __syncthreads();
    for (int off = 1; off < 512; off <<= 1) {
        int x = (t >= off) ? s[t - off] : 0;
        __syncthreads();
        s[t] += x;
        __syncthreads();
    }
    if (i < NN) g_rowptr[i] = s[t] - v;
    if (t == 511) g_bsum[blockIdx.x] = s[511];
}
// finalize: rowptr += block offsets; dinv; cnt becomes the fill cursor (= rowptr)
__global__ void k_scan3() {
    __shared__ int sb[256];
    int t = threadIdx.x;
    int v = (t < NBLK) ? g_bsum[t] : 0;
    sb[t] = v;
    __syncthreads();
    for (int off = 1; off < 256; off <<= 1) {
        int x = (t >= off) ? sb[t - off] : 0;
        __syncthreads();
        sb[t] += x;
        __syncthreads();
    }
    int excl = sb[t] - v;
    __syncthreads();
    sb[t] = excl;
    __syncthreads();

    int i = blockIdx.x * blockDim.x + t;
    if (i < NN) {
        int rp = g_rowptr[i] + sb[i >> 9];
        g_rowptr[i] = rp;
        g_dinv[i] = rsqrtf((float)g_cnt[i] + 1.0f);
        g_cnt[i] = rp;                 // cursor starts at row base
    }
    if (i == 0) g_rowptr[NN] = EE;
}
__global__ void k_fill(const void* __restrict__ ei) {
    int e = blockIdx.x * blockDim.x + threadIdx.x;
    if (e < EE) {
        int d = load_edge(ei, (long long)EE + e);
        int s = load_edge(ei, e);
        int slot = atomicAdd(&g_cnt[d], 1);   // cursor == absolute slot
        g_ecol[slot] = s;
    }
}

// ---------------- weight prep: W[K][N] fp32 -> hi/lo bf16 in [N][K] (stride KP) ----------------
__global__ void k_prepW(const float* __restrict__ W, int ncol,
                        unsigned short* __restrict__ bh, unsigned short* __restrict__ bl)
{
    int e = blockIdx.x * blockDim.x + threadIdx.x;
    if (e >= ncol * KK) return;
    int k = e / ncol, n = e % ncol;
    float w = W[e];
    __nv_bfloat16 h = __float2bfloat16(w);
    __nv_bfloat16 l = __float2bfloat16(w - __bfloat162float(h));
    bh[n * KP + k] = *(unsigned short*)&h;
    bl[n * KP + k] = *(unsigned short*)&l;
}

// ---------------- input projection: h = relu(x @ W_in + b_in) ----------------
__global__ __launch_bounds__(256) void k_inproj(
    const float* __restrict__ x, const float* __restrict__ Wi,
    const float* __restrict__ bi, float* __restrict__ h)
{
    __shared__ __align__(16) float Ws[7 * 128];
    for (int t = threadIdx.x; t < 7 * 128; t += 256) Ws[t] = Wi[t];
    __syncthreads();

    int gid = blockIdx.x * 256 + threadIdx.x;
    int i = gid >> 5, c = gid & 31;
    if (i >= NN) return;

    float xr[7];
#pragma unroll
    for (int k = 0; k < 7; k++) xr[k] = x[i * 7 + k];

    const float4* Ws4 = (const float4*)Ws;
    float4 acc = ((const float4*)bi)[c];
#pragma unroll
    for (int k = 0; k < 7; k++) {
        float4 w = Ws4[k * 32 + c];
        acc.x = fmaf(xr[k], w.x, acc.x);
        acc.y = fmaf(xr[k], w.y, acc.y);
        acc.z = fmaf(xr[k], w.z, acc.z);
        acc.w = fmaf(xr[k], w.w, acc.w);
    }
    acc.x = fmaxf(acc.x, 0.f); acc.y = fmaxf(acc.y, 0.f);
    acc.z = fmaxf(acc.z, 0.f); acc.w = fmaxf(acc.w, 0.f);
    ((float4*)h)[i * 32 + c] = acc;
}

// ---------------- tensor-core GEMM via mma.sync: Hout(fp16) = dinv .* (A[N,128] @ W) ----------------
template <int NCOL>
__global__ __launch_bounds__(256) void k_mma(
    const float* __restrict__ A,
    const unsigned short* __restrict__ BH, const unsigned short* __restrict__ BL,
    __half* __restrict__ Hout)
{
    extern __shared__ unsigned short sm[];
    constexpr int A_HI = 0;
    constexpr int A_LO = 128 * KP;
    constexpr int B_HI = 2 * 128 * KP;
    constexpr int B_LO = 2 * 128 * KP + NCOL * KP;
    constexpr int WN = NCOL / 2;
    constexpr int NT = WN / 8;

    int tid = threadIdx.x;
    int wid = tid >> 5, lane = tid & 31;
    int g = lane >> 2, t = lane & 3;
    int wm = wid & 3, wn = wid >> 2;
    int m0 = blockIdx.x * 128;

    // ---- stage A: fp32 -> hi/lo bf16, padded smem ----
#pragma unroll 4
    for (int j = 0; j < 16; j++) {
        int i = tid + j * 256;
        int m = i >> 5, k4 = i & 31, k = k4 << 2;
        int row = min(m0 + m, NN - 1);
        float4 a = ((const float4*)A)[(size_t)row * 32 + k4];
        __nv_bfloat16 h0 = __float2bfloat16(a.x), h1 = __float2bfloat16(a.y);
        __nv_bfloat16 h2 = __float2bfloat16(a.z), h3 = __float2bfloat16(a.w);
        __nv_bfloat16 l0 = __float2bfloat16(a.x - __bfloat162float(h0));
        __nv_bfloat16 l1 = __float2bfloat16(a.y - __bfloat162float(h1));
        __nv_bfloat16 l2 = __float2bfloat16(a.z - __bfloat162float(h2));
        __nv_bfloat16 l3 = __float2bfloat16(a.w - __bfloat162float(h3));
        uint32_t h01 = ((uint32_t)*(unsigned short*)&h1 << 16) | *(unsigned short*)&h0;
        uint32_t h23 = ((uint32_t)*(unsigned short*)&h3 << 16) | *(unsigned short*)&h2;
        uint32_t l01 = ((uint32_t)*(unsigned short*)&l1 << 16) | *(unsigned short*)&l0;
        uint32_t l23 = ((uint32_t)*(unsigned short*)&l3 << 16) | *(unsigned short*)&l2;
        *(uint2*)&sm[A_HI + m * KP + k] = make_uint2(h01, h23);
        *(uint2*)&sm[A_LO + m * KP + k] = make_uint2(l01, l23);
    }
    // ---- stage B: raw copy ----
    {
        constexpr int CNT = NCOL * KP / 8;
        const uint4* gh = (const uint4*)BH;
        const uint4* gl = (const uint4*)BL;
        uint4* shh = (uint4*)&sm[B_HI];
        uint4* sll = (uint4*)&sm[B_LO];
        for (int i = tid; i < CNT; i += 256) { shh[i] = gh[i]; sll[i] = gl[i]; }
    }
    __syncthreads();

    float acc[2][NT][4];
#pragma unroll
    for (int mt = 0; mt < 2; mt++)
#pragma unroll
        for (int nt = 0; nt < NT; nt++)
#pragma unroll
            for (int q = 0; q < 4; q++) acc[mt][nt][q] = 0.f;

#pragma unroll
    for (int pass = 0; pass < 3; pass++) {
        const unsigned short* aS = sm + ((pass == 1) ? A_LO : A_HI);
        const unsigned short* bS = sm + ((pass == 2) ? B_LO : B_HI);
        int am = wm * 32;
#pragma unroll
        for (int k0 = 0; k0 < 128; k0 += 16) {
            uint32_t af[2][4];
#pragma unroll
            for (int mt = 0; mt < 2; mt++) {
                int r = am + mt * 16 + g;
                af[mt][0] = *(const uint32_t*)(aS + r * KP + k0 + t * 2);
                af[mt][1] = *(const uint32_t*)(aS + (r + 8) * KP + k0 + t * 2);
                af[mt][2] = *(const uint32_t*)(aS + r * KP + k0 + 8 + t * 2);
                af[mt][3] = *(const uint32_t*)(aS + (r + 8) * KP + k0 + 8 + t * 2);
            }
#pragma unroll
            for (int nt = 0; nt < NT; nt++) {
                int n = wn * WN + nt * 8 + g;
                uint32_t b0 = *(const uint32_t*)(bS + n * KP + k0 + t * 2);
                uint32_t b1 = *(const uint32_t*)(bS + n * KP + k0 + 8 + t * 2);
                mma16816(acc[0][nt], af[0], b0, b1);
                mma16816(acc[1][nt], af[1], b0, b1);
            }
        }
    }

    // ---- epilogue: premultiply by dinv[row], fp16 stores ----
#pragma unroll
    for (int mt = 0; mt < 2; mt++) {
        int r0 = m0 + wm * 32 + mt * 16 + g;
        int r1 = r0 + 8;
        if (r0 < NN) {
            float dv = g_dinv[r0];
#pragma unroll
            for (int nt = 0; nt < NT; nt++) {
                int c = wn * WN + nt * 8 + t * 2;
                *(__half2*)&Hout[(size_t)r0 * NCOL + c] =
                    __floats2half2_rn(acc[mt][nt][0] * dv, acc[mt][nt][1] * dv);
            }
        }
        if (r1 < NN) {
            float dv = g_dinv[r1];
#pragma unroll
            for (int nt = 0; nt < NT; nt++) {
                int c = wn * WN + nt * 8 + t * 2;
                *(__half2*)&Hout[(size_t)r1 * NCOL + c] =
                    __floats2half2_rn(acc[mt][nt][2] * dv, acc[mt][nt][3] * dv);
            }
        }
    }
}

// ---------------- fused agg (premultiplied fp16 gather) + bias + BN + relu + residual (width 128) ----------------
__global__ __launch_bounds__(256) void k_agg128(
    const __half* __restrict__ linH, const float* __restrict__ resid,
    const float* __restrict__ bias, const float* __restrict__ gam,
    const float* __restrict__ bet, const float* __restrict__ mea,
    const float* __restrict__ var, float* __restrict__ out)
{
    __shared__ int s_c[8][32];
    int ws = threadIdx.x >> 5;
    int w = (blockIdx.x * blockDim.x + threadIdx.x) >> 5;
    int lane = threadIdx.x & 31;
    if (w >= NN) return;

    int start = g_rowptr[w], end = g_rowptr[w + 1];
    float di = g_dinv[w];
    const uint2* linH2 = (const uint2*)linH;   // 4 halves per lane

    float4 acc = make_float4(0.f, 0.f, 0.f, 0.f);
    for (int e0 = start; e0 < end; e0 += 32) {
        int idx = e0 + lane;
        if (idx < end) s_c[ws][lane] = g_ecol[idx];
        __syncwarp();
        int nn = min(32, end - e0);
        int j = 0;
#pragma unroll 1
        for (; j + 4 <= nn; j += 4) {
            int c0 = s_c[ws][j + 0];
            int c1 = s_c[ws][j + 1];
            int c2 = s_c[ws][j + 2];
            int c3 = s_c[ws][j + 3];
            uint2 u0 = linH2[c0 * 32 + lane];
            uint2 u1 = linH2[c1 * 32 + lane];
            uint2 u2 = linH2[c2 * 32 + lane];
            uint2 u3 = linH2[c3 * 32 + lane];
            float2 a0 = __half22float2(*(__half2*)&u0.x), b0 = __half22float2(*(__half2*)&u0.y);
            float2 a1 = __half22float2(*(__half2*)&u1.x), b1 = __half22float2(*(__half2*)&u1.y);
            float2 a2 = __half22float2(*(__half2*)&u2.x), b2 = __half22float2(*(__half2*)&u2.y);
            float2 a3 = __half22float2(*(__half2*)&u3.x), b3 = __half22float2(*(__half2*)&u3.y);
            acc.x += a0.x + a1.x; acc.y += a0.y + a1.y;
            acc.z += b0.x + b1.x; acc.w += b0.y + b1.y;
            acc.x += a2.x + a3.x; acc.y += a2.y + a3.y;
            acc.z += b2.x + b3.x; acc.w += b2.y + b3.y;
        }
        for (; j < nn; j++) {
            int c = s_c[ws][j];
            uint2 u = linH2[c * 32 + lane];
            float2 a = __half22float2(*(__half2*)&u.x);
            float2 b = __half22float2(*(__half2*)&u.y);
            acc.x += a.x; acc.y += a.y;
            acc.z += b.x; acc.w += b.y;
        }
        __syncwarp();
    }
    // self term: + hs[w] (then whole sum * di)
    uint2 su = linH2[w * 32 + lane];
    float2 s0 = __half22float2(*(__half2*)&su.x);
    float2 s1 = __half22float2(*(__half2*)&su.y);
    acc.x += s0.x; acc.y += s0.y; acc.z += s1.x; acc.w += s1.y;

    float4 bb = ((const float4*)bias)[lane];
    float4 gg = ((const float4*)gam)[lane];
    float4 ee = ((const float4*)bet)[lane];
    float4 mm = ((const float4*)mea)[lane];
    float4 vv = ((const float4*)var)[lane];
    float sx = gg.x * rsqrtf(vv.x + 1e-5f);
    float sy = gg.y * rsqrtf(vv.y + 1e-5f);
    float sz = gg.z * rsqrtf(vv.z + 1e-5f);
    float sw = gg.w * rsqrtf(vv.w + 1e-5f);

    float4 rr = ((const float4*)resid)[w * 32 + lane];
    float4 o;
    o.x = fmaxf((fmaf(acc.x, di, bb.x) - mm.x) * sx + ee.x, 0.f) + rr.x;
    o.y = fmaxf((fmaf(acc.y, di, bb.y) - mm.y) * sy + ee.y, 0.f) + rr.y;
    o.z = fmaxf((fmaf(acc.z, di, bb.z) - mm.z) * sz + ee.z, 0.f) + rr.z;
    o.w = fmaxf((fmaf(acc.w, di, bb.w) - mm.w) * sw + ee.w, 0.f) + rr.w;
    ((float4*)out)[w * 32 + lane] = o;
}

// ---------------- final layer agg (width 64): conv + bias + BN only ----------------
__global__ __launch_bounds__(256) void k_agg64(
    const __half* __restrict__ linH,
    const float* __restrict__ bias, const float* __restrict__ gam,
    const float* __restrict__ bet, const float* __restrict__ mea,
    const float* __restrict__ var, float* __restrict__ out)
{
    __shared__ int s_c[8][32];
    int ws = threadIdx.x >> 5;
    int w = (blockIdx.x * blockDim.x + threadIdx.x) >> 5;
    int lane = threadIdx.x & 31;
    if (w >= NN) return;

    int start = g_rowptr[w], end = g_rowptr[w + 1];
    float di = g_dinv[w];
    const __half2* linH2 = (const __half2*)linH;   // 2 halves per lane

    float2 acc = make_float2(0.f, 0.f);
    for (int e0 = start; e0 < end; e0 += 32) {
        int idx = e0 + lane;
        if (idx < end) s_c[ws][lane] = g_ecol[idx];
        __syncwarp();
        int nn = min(32, end - e0);
        int j = 0;
#pragma unroll 1
        for (; j + 4 <= nn; j += 4) {
            int c0 = s_c[ws][j + 0];
            int c1 = s_c[ws][j + 1];
            int c2 = s_c[ws][j + 2];
            int c3 = s_c[ws][j + 3];
            float2 f0 = __half22float2(linH2[c0 * 32 + lane]);
            float2 f1 = __half22float2(linH2[c1 * 32 + lane]);
            float2 f2 = __half22float2(linH2[c2 * 32 + lane]);
            float2 f3 = __half22float2(linH2[c3 * 32 + lane]);
            acc.x += f0.x + f1.x; acc.y += f0.y + f1.y;
            acc.x += f2.x + f3.x; acc.y += f2.y + f3.y;
        }
        for (; j < nn; j++) {
            int c = s_c[ws][j];
            float2 f = __half22float2(linH2[c * 32 + lane]);
            acc.x += f.x; acc.y += f.y;
        }
        __syncwarp();
    }
    float2 sv = __half22float2(linH2[w * 32 + lane]);
    acc.x += sv.x; acc.y += sv.y;

    float2 bb = ((const float2*)bias)[lane];
    float2 gg = ((const float2*)gam)[lane];
    float2 ee = ((const float2*)bet)[lane];
    float2 mm = ((const float2*)mea)[lane];
    float2 vv = ((const float2*)var)[lane];
    float sx = gg.x * rsqrtf(vv.x + 1e-5f);
    float sy = gg.y * rsqrtf(vv.y + 1e-5f);

    float2 o;
    o.x = (fmaf(acc.x, di, bb.x) - mm.x) * sx + ee.x;
    o.y = (fmaf(acc.y, di, bb.y) - mm.y) * sy + ee.y;
    ((float2*)out)[w * 32 + lane] = o;
}

// ---------------- launch ----------------
extern "C" void kernel_launch(void* const* d_in, const int* in_sizes, int n_in,
                              void* d_out, int out_size)
{
    const float* x    = (const float*)d_in[0];
    const void*  ei   = d_in[1];
    const float* W_in = (const float*)d_in[2];
    const float* b_in = (const float*)d_in[3];
    const float* W0 = (const float*)d_in[4];
    const float* b0 = (const float*)d_in[5];
    const float* g0 = (const float*)d_in[6];
    const float* e0 = (const float*)d_in[7];
    const float* m0 = (const float*)d_in[8];
    const float* v0 = (const float*)d_in[9];
    const float* W1 = (const float*)d_in[10];
    const float* b1 = (const float*)d_in[11];
    const float* g1 = (const float*)d_in[12];
    const float* e1 = (const float*)d_in[13];
    const float* m1 = (const float*)d_in[14];
    const float* v1 = (const float*)d_in[15];
    const float* W2 = (const float*)d_in[16];
    const float* b2 = (const float*)d_in[17];
    const float* g2 = (const float*)d_in[18];
    const float* e2 = (const float*)d_in[19];
    const float* m2 = (const float*)d_in[20];
    const float* v2 = (const float*)d_in[21];
    float* out = (float*)d_out;

    float *bufA, *bufC;
    __half* bufH;
    unsigned short* wsp;
    cudaGetSymbolAddress((void**)&bufA, g_bufA);
    cudaGetSymbolAddress((void**)&bufC, g_bufC);
    cudaGetSymbolAddress((void**)&bufH, g_bufH);
    cudaGetSymbolAddress((void**)&wsp,  g_Wsplit);
    unsigned short* WH0 = wsp + 0 * 128 * KP;
    unsigned short* WL0 = wsp + 1 * 128 * KP;
    unsigned short* WH1 = wsp + 2 * 128 * KP;
    unsigned short* WL1 = wsp + 3 * 128 * KP;
    unsigned short* WH2 = wsp + 4 * 128 * KP;
    unsigned short* WL2 = wsp + 5 * 128 * KP;

    const int SM128 = (2 * 128 * KP + 2 * 128 * KP) * 2;  // 139264 B
    const int SM64  = (2 * 128 * KP + 2 * 64 * KP) * 2;   // 104448 B
    cudaFuncSetAttribute(k_mma<128>, cudaFuncAttributeMaxDynamicSharedMemorySize, SM128);
    cudaFuncSetAttribute(k_mma<64>,  cudaFuncAttributeMaxDynamicSharedMemorySize, SM64);

    // lazily created side stream + fork/join events (resources only; work identical per call)
    static cudaStream_t s2 = nullptr;
    static cudaEvent_t evStart = nullptr, evPrep = nullptr, evScan = nullptr, evFill = nullptr;
    if (!s2) {
        cudaStreamCreateWithFlags(&s2, cudaStreamNonBlocking);
        cudaEventCreateWithFlags(&evStart, cudaEventDisableTiming);
        cudaEventCreateWithFlags(&evPrep,  cudaEventDisableTiming);
        cudaEventCreateWithFlags(&evScan,  cudaEventDisableTiming);
        cudaEventCreateWithFlags(&evFill,  cudaEventDisableTiming);
    }

    // ---- fork: side stream does weight prep + input projection ----
    cudaEventRecord(evStart, 0);
    cudaStreamWaitEvent(s2, evStart, 0);
    k_prepW<<<64, 256, 0, s2>>>(W0, 128, WH0, WL0);
    k_prepW<<<64, 256, 0, s2>>>(W1, 128, WH1, WL1);
    k_prepW<<<32, 256, 0, s2>>>(W2, 64,  WH2, WL2);
    k_inproj<<<(NN * 32 + 255) / 256, 256, 0, s2>>>(x, W_in, b_in, bufA);
    cudaEventRecord(evPrep, s2);

    // ---- main stream: CSR counts + scan (degrees/dinv ready after scan3) ----
    k_zerodetect<<<(NN + 255) / 256, 256>>>((const unsigned int*)ei);
    k_hist<<<(EE + 255) / 256, 256>>>(ei);
    k_scan1<<<NBLK, 512>>>();
    k_scan3<<<(NN + 255) / 256, 256>>>();
    cudaEventRecord(evScan, 0);

    // ---- side stream: fill runs concurrently with gemm0 ----
    cudaStreamWaitEvent(s2, evScan, 0);
    k_fill<<<(EE + 255) / 256, 256, 0, s2>>>(ei);
    cudaEventRecord(evFill, s2);

    const int GB = (NN + 127) / 128;  // 782
    // ---- main stream: gemm0 (needs inproj + dinv), then join fill before agg0 ----
    cudaStreamWaitEvent(0, evPrep, 0);
    k_mma<128><<<GB, 256, SM128>>>(bufA, WH0, WL0, bufH);
    cudaStreamWaitEvent(0, evFill, 0);
    k_agg128<<<(NN * 32 + 255) / 256, 256>>>(bufH, bufA, b0, g0, e0, m0, v0, bufC);
    // layer 1
    k_mma<128><<<GB, 256, SM128>>>(bufC, WH1, WL1, bufH);
    k_agg128<<<(NN * 32 + 255) / 256, 256>>>(bufH, bufC, b1, g1, e1, m1, v1, bufA);
    // layer 2 (final)
    k_mma<64><<<GB, 256, SM64>>>(bufA, WH2, WL2, bufH);
    k_agg64<<<(NN * 32 + 255) / 256, 256>>>(bufH, b2, g2, e2, m2, v2, out);
}

// round 14
// speedup vs baseline: 1.4640x; 1.0109x over previous
#include <cuda_runtime.h>
#include <cuda_bf16.h>
#include <cuda_fp16.h>
#include <cstdint>

#define NN 100000
#define EE 3200000
#define KK 128
#define KP 136      // padded smem row stride (elems): 272B = 68 words -> conflict-free frags
#define CAP 80      // fixed bucket capacity per node (deg ~ Poisson(32), max@100K ~59)
#define SPILLMAX 4096

// ---------------- scratch (device globals; no allocations) ----------------
__device__ float g_bufA[NN * 128];
__device__ float g_bufC[NN * 128];
__device__ __half g_bufH[NN * 128];   // fp16 premultiplied GEMM output: hs = dinv*h
__device__ int   g_cnt[NN];           // slot cursor during fill; == degree afterwards
__device__ int   g_ecol[NN * CAP];    // fixed-stride edge buckets
__device__ int2  g_spill[SPILLMAX];   // overflow edges {dst, src} (expected empty)
__device__ int   g_spillCnt;
__device__ int   g_is64;
// split weights, [N][K] layout with stride KP
__device__ unsigned short g_Wsplit[6][128 * KP];

// ---------------- warp mma helper (baseline PTX, valid on sm_103) ----------------
__device__ __forceinline__ void mma16816(float* c, const uint32_t* a, uint32_t b0, uint32_t b1) {
    asm volatile(
        "mma.sync.aligned.m16n8k16.row.col.f32.bf16.bf16.f32 "
        "{%0,%1,%2,%3}, {%4,%5,%6,%7}, {%8,%9}, {%0,%1,%2,%3};"
        : "+f"(c[0]), "+f"(c[1]), "+f"(c[2]), "+f"(c[3])
        : "r"(a[0]), "r"(a[1]), "r"(a[2]), "r"(a[3]), "r"(b0), "r"(b1));
}

// ---------------- zero counters + edge dtype detection (merged) ----------------
__global__ void k_zerodetect(const unsigned int* __restrict__ ei_raw) {
    int i = blockIdx.x * blockDim.x + threadIdx.x;
    if (i < NN) g_cnt[i] = 0;
    if (i == 0) g_spillCnt = 0;
    if (blockIdx.x == 0) {
        __shared__ unsigned int red[8];
        unsigned int o = 0;
        for (int j = threadIdx.x; j < 2048; j += 256) o |= ei_raw[2 * j + 1];
#pragma unroll
        for (int off = 16; off; off >>= 1) o |= __shfl_xor_sync(0xffffffffu, o, off);
        if ((threadIdx.x & 31) == 0) red[threadIdx.x >> 5] = o;
        __syncthreads();
        if (threadIdx.x == 0) {
            unsigned int t = 0;
#pragma unroll
            for (int j = 0; j < 8; j++) t |= red[j];
            g_is64 = (t == 0u) ? 1 : 0;
        }
    }
}

__device__ __forceinline__ int clampN(long long v) {
    return (int)min((long long)(NN - 1), max(0ll, v));
}

// ---------------- single-pass bucket fill (2 edges/thread, vector loads) ----------------
__global__ void k_fillc(const void* __restrict__ ei) {
    int t = blockIdx.x * blockDim.x + threadIdx.x;   // pair index
    if (t >= EE / 2) return;
    int d0, d1, s0, s1;
    if (g_is64) {
        const longlong2* p64 = (const longlong2*)ei;
        longlong2 dd = p64[EE / 2 + t];
        longlong2 ss = p64[t];
        d0 = clampN(dd.x); d1 = clampN(dd.y);
        s0 = clampN(ss.x); s1 = clampN(ss.y);
    } else {
        const int2* p32 = (const int2*)ei;
        int2 dd = p32[EE / 2 + t];
        int2 ss = p32[t];
        d0 = clampN(dd.x); d1 = clampN(dd.y);
        s0 = clampN(ss.x); s1 = clampN(ss.y);
    }
    int slot0 = atomicAdd(&g_cnt[d0], 1);
    if (slot0 < CAP) g_ecol[d0 * CAP + slot0] = s0;
    else { int sp = atomicAdd(&g_spillCnt, 1); if (sp < SPILLMAX) g_spill[sp] = make_int2(d0, s0); }
    int slot1 = atomicAdd(&g_cnt[d1], 1);
    if (slot1 < CAP) g_ecol[d1 * CAP + slot1] = s1;
    else { int sp = atomicAdd(&g_spillCnt, 1); if (sp < SPILLMAX) g_spill[sp] = make_int2(d1, s1); }
}

// ---------------- weight prep: W[K][N] fp32 -> hi/lo bf16 in [N][K] (stride KP) ----------------
__global__ void k_prepW(const float* __restrict__ W, int ncol,
                        unsigned short* __restrict__ bh, unsigned short* __restrict__ bl)
{
    int e = blockIdx.x * blockDim.x + threadIdx.x;
    if (e >= ncol * KK) return;
    int k = e / ncol, n = e % ncol;
    float w = W[e];
    __nv_bfloat16 h = __float2bfloat16(w);
    __nv_bfloat16 l = __float2bfloat16(w - __bfloat162float(h));
    bh[n * KP + k] = *(unsigned short*)&h;
    bl[n * KP + k] = *(unsigned short*)&l;
}

// ---------------- input projection: h = relu(x @ W_in + b_in) ----------------
__global__ __launch_bounds__(256) void k_inproj(
    const float* __restrict__ x, const float* __restrict__ Wi,
    const float* __restrict__ bi, float* __restrict__ h)
{
    __shared__ __align__(16) float Ws[7 * 128];
    for (int t = threadIdx.x; t < 7 * 128; t += 256) Ws[t] = Wi[t];
    __syncthreads();

    int gid = blockIdx.x * 256 + threadIdx.x;
    int i = gid >> 5, c = gid & 31;
    if (i >= NN) return;

    float xr[7];
#pragma unroll
    for (int k = 0; k < 7; k++) xr[k] = x[i * 7 + k];

    const float4* Ws4 = (const float4*)Ws;
    float4 acc = ((const float4*)bi)[c];
#pragma unroll
    for (int k = 0; k < 7; k++) {
        float4 w = Ws4[k * 32 + c];
        acc.x = fmaf(xr[k], w.x, acc.x);
        acc.y = fmaf(xr[k], w.y, acc.y);
        acc.z = fmaf(xr[k], w.z, acc.z);
        acc.w = fmaf(xr[k], w.w, acc.w);
    }
    acc.x = fmaxf(acc.x, 0.f); acc.y = fmaxf(acc.y, 0.f);
    acc.z = fmaxf(acc.z, 0.f); acc.w = fmaxf(acc.w, 0.f);
    ((float4*)h)[i * 32 + c] = acc;
}

// ---------------- tensor-core GEMM via mma.sync: Hout(fp16) = dinv .* (A[N,128] @ W) ----------------
template <int NCOL>
__global__ __launch_bounds__(256) void k_mma(
    const float* __restrict__ A,
    const unsigned short* __restrict__ BH, const unsigned short* __restrict__ BL,
    __half* __restrict__ Hout)
{
    extern __shared__ unsigned short sm[];
    constexpr int A_HI = 0;
    constexpr int A_LO = 128 * KP;
    constexpr int B_HI = 2 * 128 * KP;
    constexpr int B_LO = 2 * 128 * KP + NCOL * KP;
    constexpr int WN = NCOL / 2;
    constexpr int NT = WN / 8;

    int tid = threadIdx.x;
    int wid = tid >> 5, lane = tid & 31;
    int g = lane >> 2, t = lane & 3;
    int wm = wid & 3, wn = wid >> 2;
    int m0 = blockIdx.x * 128;

    // ---- stage A: fp32 -> hi/lo bf16, padded smem ----
#pragma unroll 4
    for (int j = 0; j < 16; j++) {
        int i = tid + j * 256;
        int m = i >> 5, k4 = i & 31, k = k4 << 2;
        int row = min(m0 + m, NN - 1);
        float4 a = ((const float4*)A)[(size_t)row * 32 + k4];
        __nv_bfloat16 h0 = __float2bfloat16(a.x), h1 = __float2bfloat16(a.y);
        __nv_bfloat16 h2 = __float2bfloat16(a.z), h3 = __float2bfloat16(a.w);
        __nv_bfloat16 l0 = __float2bfloat16(a.x - __bfloat162float(h0));
        __nv_bfloat16 l1 = __float2bfloat16(a.y - __bfloat162float(h1));
        __nv_bfloat16 l2 = __float2bfloat16(a.z - __bfloat162float(h2));
        __nv_bfloat16 l3 = __float2bfloat16(a.w - __bfloat162float(h3));
        uint32_t h01 = ((uint32_t)*(unsigned short*)&h1 << 16) | *(unsigned short*)&h0;
        uint32_t h23 = ((uint32_t)*(unsigned short*)&h3 << 16) | *(unsigned short*)&h2;
        uint32_t l01 = ((uint32_t)*(unsigned short*)&l1 << 16) | *(unsigned short*)&l0;
        uint32_t l23 = ((uint32_t)*(unsigned short*)&l3 << 16) | *(unsigned short*)&l2;
        *(uint2*)&sm[A_HI + m * KP + k] = make_uint2(h01, h23);
        *(uint2*)&sm[A_LO + m * KP + k] = make_uint2(l01, l23);
    }
    // ---- stage B: raw copy ----
    {
        constexpr int CNT = NCOL * KP / 8;
        const uint4* gh = (const uint4*)BH;
        const uint4* gl = (const uint4*)BL;
        uint4* shh = (uint4*)&sm[B_HI];
        uint4* sll = (uint4*)&sm[B_LO];
        for (int i = tid; i < CNT; i += 256) { shh[i] = gh[i]; sll[i] = gl[i]; }
    }
    __syncthreads();

    float acc[2][NT][4];
#pragma unroll
    for (int mt = 0; mt < 2; mt++)
#pragma unroll
        for (int nt = 0; nt < NT; nt++)
#pragma unroll
            for (int q = 0; q < 4; q++) acc[mt][nt][q] = 0.f;

#pragma unroll
    for (int pass = 0; pass < 3; pass++) {
        const unsigned short* aS = sm + ((pass == 1) ? A_LO : A_HI);
        const unsigned short* bS = sm + ((pass == 2) ? B_LO : B_HI);
        int am = wm * 32;
#pragma unroll
        for (int k0 = 0; k0 < 128; k0 += 16) {
            uint32_t af[2][4];
#pragma unroll
            for (int mt = 0; mt < 2; mt++) {
                int r = am + mt * 16 + g;
                af[mt][0] = *(const uint32_t*)(aS + r * KP + k0 + t * 2);
                af[mt][1] = *(const uint32_t*)(aS + (r + 8) * KP + k0 + t * 2);
                af[mt][2] = *(const uint32_t*)(aS + r * KP + k0 + 8 + t * 2);
                af[mt][3] = *(const uint32_t*)(aS + (r + 8) * KP + k0 + 8 + t * 2);
            }
#pragma unroll
            for (int nt = 0; nt < NT; nt++) {
                int n = wn * WN + nt * 8 + g;
                uint32_t b0 = *(const uint32_t*)(bS + n * KP + k0 + t * 2);
                uint32_t b1 = *(const uint32_t*)(bS + n * KP + k0 + 8 + t * 2);
                mma16816(acc[0][nt], af[0], b0, b1);
                mma16816(acc[1][nt], af[1], b0, b1);
            }
        }
    }

    // ---- epilogue: premultiply by dinv(row) = rsqrt(deg+1), fp16 stores ----
#pragma unroll
    for (int mt = 0; mt < 2; mt++) {
        int r0 = m0 + wm * 32 + mt * 16 + g;
        int r1 = r0 + 8;
        if (r0 < NN) {
            float dv = rsqrtf((float)g_cnt[r0] + 1.0f);
#pragma unroll
            for (int nt = 0; nt < NT; nt++) {
                int c = wn * WN + nt * 8 + t * 2;
                *(__half2*)&Hout[(size_t)r0 * NCOL + c] =
                    __floats2half2_rn(acc[mt][nt][0] * dv, acc[mt][nt][1] * dv);
            }
        }
        if (r1 < NN) {
            float dv = rsqrtf((float)g_cnt[r1] + 1.0f);
#pragma unroll
            for (int nt = 0; nt < NT; nt++) {
                int c = wn * WN + nt * 8 + t * 2;
                *(__half2*)&Hout[(size_t)r1 * NCOL + c] =
                    __floats2half2_rn(acc[mt][nt][2] * dv, acc[mt][nt][3] * dv);
            }
        }
    }
}

// ---------------- fused agg (premultiplied fp16 gather) + bias + BN + relu + residual (width 128) ----------------
__global__ __launch_bounds__(256) void k_agg128(
    const __half* __restrict__ linH, const float* __restrict__ resid,
    const float* __restrict__ bias, const float* __restrict__ gam,
    const float* __restrict__ bet, const float* __restrict__ mea,
    const float* __restrict__ var, float* __restrict__ out)
{
    __shared__ int s_c[8][32];
    int ws = threadIdx.x >> 5;
    int w = (blockIdx.x * blockDim.x + threadIdx.x) >> 5;
    int lane = threadIdx.x & 31;
    if (w >= NN) return;

    int deg = g_cnt[w];
    float di = rsqrtf((float)deg + 1.0f);
    int start = w * CAP, end = start + min(deg, CAP);
    const uint2* linH2 = (const uint2*)linH;   // 4 halves per lane

    float4 acc = make_float4(0.f, 0.f, 0.f, 0.f);
    for (int e0 = start; e0 < end; e0 += 32) {
        int idx = e0 + lane;
        if (idx < end) s_c[ws][lane] = g_ecol[idx];
        __syncwarp();
        int nn = min(32, end - e0);
        int j = 0;
#pragma unroll 1
        for (; j + 4 <= nn; j += 4) {
            int c0 = s_c[ws][j + 0];
            int c1 = s_c[ws][j + 1];
            int c2 = s_c[ws][j + 2];
            int c3 = s_c[ws][j + 3];
            uint2 u0 = linH2[c0 * 32 + lane];
            uint2 u1 = linH2[c1 * 32 + lane];
            uint2 u2 = linH2[c2 * 32 + lane];
            uint2 u3 = linH2[c3 * 32 + lane];
            float2 a0 = __half22float2(*(__half2*)&u0.x), b0 = __half22float2(*(__half2*)&u0.y);
            float2 a1 = __half22float2(*(__half2*)&u1.x), b1 = __half22float2(*(__half2*)&u1.y);
            float2 a2 = __half22float2(*(__half2*)&u2.x), b2 = __half22float2(*(__half2*)&u2.y);
            float2 a3 = __half22float2(*(__half2*)&u3.x), b3 = __half22float2(*(__half2*)&u3.y);
            acc.x += a0.x + a1.x; acc.y += a0.y + a1.y;
            acc.z += b0.x + b1.x; acc.w += b0.y + b1.y;
            acc.x += a2.x + a3.x; acc.y += a2.y + a3.y;
            acc.z += b2.x + b3.x; acc.w += b2.y + b3.y;
        }
        for (; j < nn; j++) {
            int c = s_c[ws][j];
            uint2 u = linH2[c * 32 + lane];
            float2 a = __half22float2(*(__half2*)&u.x);
            float2 b = __half22float2(*(__half2*)&u.y);
            acc.x += a.x; acc.y += a.y;
            acc.z += b.x; acc.w += b.y;
        }
        __syncwarp();
    }
    // overflow edges (expected none)
    int sc = g_spillCnt;
    for (int i = 0; i < sc && i < SPILLMAX; i++) {
        int2 p = g_spill[i];
        if (p.x == w) {
            uint2 u = linH2[p.y * 32 + lane];
            float2 a = __half22float2(*(__half2*)&u.x);
            float2 b = __half22float2(*(__half2*)&u.y);
            acc.x += a.x; acc.y += a.y;
            acc.z += b.x; acc.w += b.y;
        }
    }
    // self term: + hs[w] (then whole sum * di)
    uint2 su = linH2[w * 32 + lane];
    float2 s0 = __half22float2(*(__half2*)&su.x);
    float2 s1 = __half22float2(*(__half2*)&su.y);
    acc.x += s0.x; acc.y += s0.y; acc.z += s1.x; acc.w += s1.y;

    float4 bb = ((const float4*)bias)[lane];
    float4 gg = ((const float4*)gam)[lane];
    float4 ee = ((const float4*)bet)[lane];
    float4 mm = ((const float4*)mea)[lane];
    float4 vv = ((const float4*)var)[lane];
    float sx = gg.x * rsqrtf(vv.x + 1e-5f);
    float sy = gg.y * rsqrtf(vv.y + 1e-5f);
    float sz = gg.z * rsqrtf(vv.z + 1e-5f);
    float sw = gg.w * rsqrtf(vv.w + 1e-5f);

    float4 rr = ((const float4*)resid)[w * 32 + lane];
    float4 o;
    o.x = fmaxf((fmaf(acc.x, di, bb.x) - mm.x) * sx + ee.x, 0.f) + rr.x;
    o.y = fmaxf((fmaf(acc.y, di, bb.y) - mm.y) * sy + ee.y, 0.f) + rr.y;
    o.z = fmaxf((fmaf(acc.z, di, bb.z) - mm.z) * sz + ee.z, 0.f) + rr.z;
    o.w = fmaxf((fmaf(acc.w, di, bb.w) - mm.w) * sw + ee.w, 0.f) + rr.w;
    ((float4*)out)[w * 32 + lane] = o;
}

// ---------------- final layer agg (width 64): conv + bias + BN only ----------------
__global__ __launch_bounds__(256) void k_agg64(
    const __half* __restrict__ linH,
    const float* __restrict__ bias, const float* __restrict__ gam,
    const float* __restrict__ bet, const float* __restrict__ mea,
    const float* __restrict__ var, float* __restrict__ out)
{
    __shared__ int s_c[8][32];
    int ws = threadIdx.x >> 5;
    int w = (blockIdx.x * blockDim.x + threadIdx.x) >> 5;
    int lane = threadIdx.x & 31;
    if (w >= NN) return;

    int deg = g_cnt[w];
    float di = rsqrtf((float)deg + 1.0f);
    int start = w * CAP, end = start + min(deg, CAP);
    const __half2* linH2 = (const __half2*)linH;   // 2 halves per lane

    float2 acc = make_float2(0.f, 0.f);
    for (int e0 = start; e0 < end; e0 += 32) {
        int idx = e0 + lane;
        if (idx < end) s_c[ws][lane] = g_ecol[idx];
        __syncwarp();
        int nn = min(32, end - e0);
        int j = 0;
#pragma unroll 1
        for (; j + 4 <= nn; j += 4) {
            int c0 = s_c[ws][j + 0];
            int c1 = s_c[ws][j + 1];
            int c2 = s_c[ws][j + 2];
            int c3 = s_c[ws][j + 3];
            float2 f0 = __half22float2(linH2[c0 * 32 + lane]);
            float2 f1 = __half22float2(linH2[c1 * 32 + lane]);
            float2 f2 = __half22float2(linH2[c2 * 32 + lane]);
            float2 f3 = __half22float2(linH2[c3 * 32 + lane]);
            acc.x += f0.x + f1.x; acc.y += f0.y + f1.y;
            acc.x += f2.x + f3.x; acc.y += f2.y + f3.y;
        }
        for (; j < nn; j++) {
            int c = s_c[ws][j];
            float2 f = __half22float2(linH2[c * 32 + lane]);
            acc.x += f.x; acc.y += f.y;
        }
        __syncwarp();
    }
    int sc = g_spillCnt;
    for (int i = 0; i < sc && i < SPILLMAX; i++) {
        int2 p = g_spill[i];
        if (p.x == w) {
            float2 f = __half22float2(linH2[p.y * 32 + lane]);
            acc.x += f.x; acc.y += f.y;
        }
    }
    float2 sv = __half22float2(linH2[w * 32 + lane]);
    acc.x += sv.x; acc.y += sv.y;

    float2 bb = ((const float2*)bias)[lane];
    float2 gg = ((const float2*)gam)[lane];
    float2 ee = ((const float2*)bet)[lane];
    float2 mm = ((const float2*)mea)[lane];
    float2 vv = ((const float2*)var)[lane];
    float sx = gg.x * rsqrtf(vv.x + 1e-5f);
    float sy = gg.y * rsqrtf(vv.y + 1e-5f);

    float2 o;
    o.x = (fmaf(acc.x, di, bb.x) - mm.x) * sx + ee.x;
    o.y = (fmaf(acc.y, di, bb.y) - mm.y) * sy + ee.y;
    ((float2*)out)[w * 32 + lane] = o;
}

// ---------------- launch ----------------
extern "C" void kernel_launch(void* const* d_in, const int* in_sizes, int n_in,
                              void* d_out, int out_size)
{
    const float* x    = (const float*)d_in[0];
    const void*  ei   = d_in[1];
    const float* W_in = (const float*)d_in[2];
    const float* b_in = (const float*)d_in[3];
    const float* W0 = (const float*)d_in[4];
    const float* b0 = (const float*)d_in[5];
    const float* g0 = (const float*)d_in[6];
    const float* e0 = (const float*)d_in[7];
    const float* m0 = (const float*)d_in[8];
    const float* v0 = (const float*)d_in[9];
    const float* W1 = (const float*)d_in[10];
    const float* b1 = (const float*)d_in[11];
    const float* g1 = (const float*)d_in[12];
    const float* e1 = (const float*)d_in[13];
    const float* m1 = (const float*)d_in[14];
    const float* v1 = (const float*)d_in[15];
    const float* W2 = (const float*)d_in[16];
    const float* b2 = (const float*)d_in[17];
    const float* g2 = (const float*)d_in[18];
    const float* e2 = (const float*)d_in[19];
    const float* m2 = (const float*)d_in[20];
    const float* v2 = (const float*)d_in[21];
    float* out = (float*)d_out;

    float *bufA, *bufC;
    __half* bufH;
    unsigned short* wsp;
    cudaGetSymbolAddress((void**)&bufA, g_bufA);
    cudaGetSymbolAddress((void**)&bufC, g_bufC);
    cudaGetSymbolAddress((void**)&bufH, g_bufH);
    cudaGetSymbolAddress((void**)&wsp,  g_Wsplit);
    unsigned short* WH0 = wsp + 0 * 128 * KP;
    unsigned short* WL0 = wsp + 1 * 128 * KP;
    unsigned short* WH1 = wsp + 2 * 128 * KP;
    unsigned short* WL1 = wsp + 3 * 128 * KP;
    unsigned short* WH2 = wsp + 4 * 128 * KP;
    unsigned short* WL2 = wsp + 5 * 128 * KP;

    const int SM128 = (2 * 128 * KP + 2 * 128 * KP) * 2;  // 139264 B
    const int SM64  = (2 * 128 * KP + 2 * 64 * KP) * 2;   // 104448 B
    cudaFuncSetAttribute(k_mma<128>, cudaFuncAttributeMaxDynamicSharedMemorySize, SM128);
    cudaFuncSetAttribute(k_mma<64>,  cudaFuncAttributeMaxDynamicSharedMemorySize, SM64);

    // lazily created side stream + fork/join events (resources only; work identical per call)
    static cudaStream_t s2 = nullptr;
    static cudaEvent_t evStart = nullptr, evPrep = nullptr;
    if (!s2) {
        cudaStreamCreateWithFlags(&s2, cudaStreamNonBlocking);
        cudaEventCreateWithFlags(&evStart, cudaEventDisableTiming);
        cudaEventCreateWithFlags(&evPrep,  cudaEventDisableTiming);
    }

    // ---- fork: side stream does weight prep + input projection ----
    cudaEventRecord(evStart, 0);
    cudaStreamWaitEvent(s2, evStart, 0);
    k_prepW<<<64, 256, 0, s2>>>(W0, 128, WH0, WL0);
    k_prepW<<<64, 256, 0, s2>>>(W1, 128, WH1, WL1);
    k_prepW<<<32, 256, 0, s2>>>(W2, 64,  WH2, WL2);
    k_inproj<<<(NN * 32 + 255) / 256, 256, 0, s2>>>(x, W_in, b_in, bufA);
    cudaEventRecord(evPrep, s2);

    // ---- main stream: single-pass bucket CSR (counts == degrees afterwards) ----
    k_zerodetect<<<(NN + 255) / 256, 256>>>((const unsigned int*)ei);
    k_fillc<<<(EE / 2 + 255) / 256, 256>>>(ei);

    const int GB = (NN + 127) / 128;  // 782
    // ---- main stream: join prep, then the layer chain ----
    cudaStreamWaitEvent(0, evPrep, 0);
    k_mma<128><<<GB, 256, SM128>>>(bufA, WH0, WL0, bufH);
    k_agg128<<<(NN * 32 + 255) / 256, 256>>>(bufH, bufA, b0, g0, e0, m0, v0, bufC);
    // layer 1
    k_mma<128><<<GB, 256, SM128>>>(bufC, WH1, WL1, bufH);
    k_agg128<<<(NN * 32 + 255) / 256, 256>>>(bufH, bufC, b1, g1, e1, m1, v1, bufA);
    // layer 2 (final)
    k_mma<64><<<GB, 256, SM64>>>(bufA, WH2, WL2, bufH);
    k_agg64<<<(NN * 32 + 255) / 256, 256>>>(bufH, b2, g2, e2, m2, v2, out);
}